// round 1
// baseline (speedup 1.0000x reference)
#include <cuda_runtime.h>
#include <math.h>

// ---------------- problem constants ----------------
#define HH     112
#define WW     112
#define CC     128
#define WS7    7
#define SHIFT3 3
#define NH4    4
#define BB     8
#define HID    512
#define NN     49           // tokens per window
#define HD32   32           // head dim
#define NW     256          // windows per image (16x16)
#define LTOK   (HH*WW)      // 12544
#define MROWS  (BB*NW*NN)   // 100352
#define SCALEF 0.17677669529663687f  // 32^-0.5

// ---------------- scratch (static device globals; no allocation) ----------------
__device__ float g_xw  [MROWS*CC];   // LN1'd, shifted, window-partitioned tokens
__device__ float g_q   [MROWS*CC];   // (bn, h, n, d)
__device__ float g_k   [MROWS*CC];
__device__ float g_v   [MROWS*CC];
__device__ float g_obuf[MROWS*CC];   // attention output, head-concat layout (bn*49+n, 128)
__device__ float g_xres[MROWS*CC];   // shortcut + attn branch (token-major b*L layout)
__device__ float g_y   [MROWS*CC];   // LN2 output
__device__ float g_h1  [MROWS*HID];  // gelu(fc1)

// ---------------- LN1 + roll(-3,-3) + window partition ----------------
__global__ void ln1_gather_kernel(const float* __restrict__ x,
                                  const float* __restrict__ w,
                                  const float* __restrict__ b) {
    int row  = blockIdx.x * 8 + (threadIdx.x >> 5);   // windowed row 0..100351
    int lane = threadIdx.x & 31;
    int bn = row / NN, n = row - bn * NN;
    int bi = bn >> 8, win = bn & 255;
    int wi = win >> 4, wj = win & 15;
    int r = n / 7, c = n - r * 7;
    int i = wi * 7 + r, j = wj * 7 + c;
    int si = i + SHIFT3; if (si >= HH) si -= HH;
    int sj = j + SHIFT3; if (sj >= WW) sj -= WW;
    const float4* src = (const float4*)(x + ((size_t)bi * LTOK + si * WW + sj) * CC);
    float4 v = src[lane];
    float s = v.x + v.y + v.z + v.w;
    #pragma unroll
    for (int o = 16; o; o >>= 1) s += __shfl_xor_sync(0xffffffffu, s, o);
    float mean = s * (1.0f / 128.0f);
    float dx = v.x - mean, dy = v.y - mean, dz = v.z - mean, dw = v.w - mean;
    float q = dx*dx + dy*dy + dz*dz + dw*dw;
    #pragma unroll
    for (int o = 16; o; o >>= 1) q += __shfl_xor_sync(0xffffffffu, q, o);
    float inv = rsqrtf(q * (1.0f / 128.0f) + 1e-5f);
    float4 wv = ((const float4*)w)[lane];
    float4 bv = ((const float4*)b)[lane];
    float4 o4;
    o4.x = dx * inv * wv.x + bv.x;
    o4.y = dy * inv * wv.y + bv.y;
    o4.z = dz * inv * wv.z + bv.z;
    o4.w = dw * inv * wv.w + bv.w;
    ((float4*)(g_xw + (size_t)row * CC))[lane] = o4;
}

// ---------------- LN2 (token-major, no gather) ----------------
__global__ void ln2_kernel(const float* __restrict__ w, const float* __restrict__ b) {
    int row  = blockIdx.x * 8 + (threadIdx.x >> 5);
    int lane = threadIdx.x & 31;
    float4 v = ((const float4*)(g_xres + (size_t)row * CC))[lane];
    float s = v.x + v.y + v.z + v.w;
    #pragma unroll
    for (int o = 16; o; o >>= 1) s += __shfl_xor_sync(0xffffffffu, s, o);
    float mean = s * (1.0f / 128.0f);
    float dx = v.x - mean, dy = v.y - mean, dz = v.z - mean, dw = v.w - mean;
    float q = dx*dx + dy*dy + dz*dz + dw*dw;
    #pragma unroll
    for (int o = 16; o; o >>= 1) q += __shfl_xor_sync(0xffffffffu, q, o);
    float inv = rsqrtf(q * (1.0f / 128.0f) + 1e-5f);
    float4 wv = ((const float4*)w)[lane];
    float4 bv = ((const float4*)b)[lane];
    float4 o4;
    o4.x = dx * inv * wv.x + bv.x;
    o4.y = dy * inv * wv.y + bv.y;
    o4.z = dz * inv * wv.z + bv.z;
    o4.w = dw * inv * wv.w + bv.w;
    ((float4*)(g_y + (size_t)row * CC))[lane] = o4;
}

// ---------------- generic 64x64 fp32 GEMM:  C[m][o] = sum_k A[m][k]*W[o][k] ----------------
// MODE 0: A=g_xw,  OUT=384, epilogue: +qkv_b, split to g_q(*SCALE)/g_k/g_v in (bn,h,n,d) layout
// MODE 1: A=g_obuf,OUT=128, epilogue: +proj_b, un-window + roll(+3,+3) scatter, + x residual -> g_xres
// MODE 2: A=g_y,   OUT=512, epilogue: +fc1_b, exact gelu -> g_h1
// MODE 3: A=g_h1,  OUT=128, K=512, epilogue: +fc2_b + g_xres -> out
#define ROWSTRIDE 140   // floats; 35 float4 -> conflict-free LDS.128 across 8-lane phases

template<int KDIM, int MODE>
__global__ void gemm_kernel(const float* __restrict__ W,
                            const float* __restrict__ bias,
                            const float* __restrict__ xin,
                            float* __restrict__ outp) {
    extern __shared__ float sm[];
    float* As = sm;
    float* Ws = sm + 64 * ROWSTRIDE;
    const float* A = (MODE == 0) ? g_xw : (MODE == 1) ? g_obuf : (MODE == 2) ? g_y : g_h1;

    int m0 = blockIdx.x * 64;
    int o0 = blockIdx.y * 64;
    int tid = threadIdx.x;
    int ty = tid >> 4, tx = tid & 15;

    float acc[4][4];
    #pragma unroll
    for (int i = 0; i < 4; ++i)
        #pragma unroll
        for (int j = 0; j < 4; ++j) acc[i][j] = 0.0f;

    for (int k0 = 0; k0 < KDIM; k0 += 128) {
        const float4* Ag = (const float4*)(A + (size_t)m0 * KDIM + k0);
        const float4* Wg = (const float4*)(W + (size_t)o0 * KDIM + k0);
        #pragma unroll
        for (int it = 0; it < 8; ++it) {
            int idx = tid + it * 256;
            int rr = idx >> 5, c4 = idx & 31;
            float4 av = Ag[(size_t)rr * (KDIM / 4) + c4];
            *(float4*)(As + rr * ROWSTRIDE + c4 * 4) = av;
            float4 wv = Wg[(size_t)rr * (KDIM / 4) + c4];
            *(float4*)(Ws + rr * ROWSTRIDE + c4 * 4) = wv;
        }
        __syncthreads();

        const float* Ap = As + (ty * 4) * ROWSTRIDE;
        const float* Wp = Ws + (tx * 4) * ROWSTRIDE;
        #pragma unroll 4
        for (int kk = 0; kk < 128; kk += 4) {
            float4 av[4], wv[4];
            #pragma unroll
            for (int i = 0; i < 4; ++i) av[i] = *(const float4*)(Ap + i * ROWSTRIDE + kk);
            #pragma unroll
            for (int j = 0; j < 4; ++j) wv[j] = *(const float4*)(Wp + j * ROWSTRIDE + kk);
            #pragma unroll
            for (int i = 0; i < 4; ++i)
                #pragma unroll
                for (int j = 0; j < 4; ++j) {
                    acc[i][j] += av[i].x * wv[j].x;
                    acc[i][j] += av[i].y * wv[j].y;
                    acc[i][j] += av[i].z * wv[j].z;
                    acc[i][j] += av[i].w * wv[j].w;
                }
        }
        __syncthreads();
    }

    // ---------------- epilogues ----------------
    #pragma unroll
    for (int i = 0; i < 4; ++i) {
        int m = m0 + ty * 4 + i;
        if (MODE == 0) {
            int bn = m / NN, n = m - bn * NN;
            size_t base = (size_t)bn * (NH4 * NN * HD32) + n * HD32;
            #pragma unroll
            for (int j = 0; j < 4; ++j) {
                int o = o0 + tx * 4 + j;
                float val = acc[i][j] + bias[o];
                int which = o >> 7;
                int hh = (o >> 5) & 3;
                int dd = o & 31;
                size_t addr = base + (size_t)hh * (NN * HD32) + dd;
                if (which == 0)      g_q[addr] = val * SCALEF;
                else if (which == 1) g_k[addr] = val;
                else                 g_v[addr] = val;
            }
        } else if (MODE == 1) {
            int bn = m / NN, n = m - bn * NN;
            int bi = bn >> 8, win = bn & 255;
            int wi = win >> 4, wj = win & 15;
            int r = n / 7, c = n - r * 7;
            int ii = wi * 7 + r + SHIFT3; if (ii >= HH) ii -= HH;
            int jj = wj * 7 + c + SHIFT3; if (jj >= WW) jj -= WW;
            size_t tok = (size_t)bi * LTOK + ii * WW + jj;
            #pragma unroll
            for (int j = 0; j < 4; ++j) {
                int o = o0 + tx * 4 + j;
                float val = acc[i][j] + bias[o];
                g_xres[tok * CC + o] = xin[tok * CC + o] + val;
            }
        } else if (MODE == 2) {
            #pragma unroll
            for (int j = 0; j < 4; ++j) {
                int o = o0 + tx * 4 + j;
                float v = acc[i][j] + bias[o];
                float g = 0.5f * v * (1.0f + erff(v * 0.70710678118654752f));
                g_h1[(size_t)m * HID + o] = g;
            }
        } else {  // MODE 3
            #pragma unroll
            for (int j = 0; j < 4; ++j) {
                int o = o0 + tx * 4 + j;
                float val = acc[i][j] + bias[o] + g_xres[(size_t)m * CC + o];
                outp[(size_t)m * CC + o] = val;
            }
        }
    }
}

// ---------------- windowed attention: one block per (window, head) ----------------
__device__ __forceinline__ int regionf(int i) { return (i < 105) ? 0 : ((i < 109) ? 1 : 2); }

__global__ void attn_kernel(const float* __restrict__ rpb) {
    int bn = blockIdx.x;
    int h  = blockIdx.y;
    __shared__ float qs[NN * HD32];
    __shared__ float ks[NN * HD32];
    __shared__ float vs[NN * HD32];
    __shared__ float sc[NN * 50];
    int tid = threadIdx.x;

    size_t base = ((size_t)(bn * NH4 + h)) * NN * HD32;
    for (int idx = tid; idx < (NN * HD32) / 4; idx += 256) {
        ((float4*)qs)[idx] = ((const float4*)(g_q + base))[idx];
        ((float4*)ks)[idx] = ((const float4*)(g_k + base))[idx];
        ((float4*)vs)[idx] = ((const float4*)(g_v + base))[idx];
    }
    __syncthreads();

    int win = bn & 255, wi = win >> 4, wj = win & 15;
    for (int idx = tid; idx < NN * NN; idx += 256) {
        int n = idx / NN, m = idx - n * NN;
        const float4* qp = (const float4*)(qs + n * HD32);
        const float4* kp = (const float4*)(ks + m * HD32);
        float acc = 0.0f;
        #pragma unroll
        for (int d = 0; d < 8; ++d) {
            float4 a = qp[d], b = kp[d];
            acc += a.x * b.x + a.y * b.y + a.z * b.z + a.w * b.w;
        }
        int r1 = n / 7, c1 = n - r1 * 7;
        int r2 = m / 7, c2 = m - r2 * 7;
        int bidx = (r1 - r2 + 6) * 13 + (c1 - c2 + 6);
        acc += rpb[bidx * NH4 + h];
        int reg1 = regionf(wi * 7 + r1) * 3 + regionf(wj * 7 + c1);
        int reg2 = regionf(wi * 7 + r2) * 3 + regionf(wj * 7 + c2);
        if (reg1 != reg2) acc -= 100.0f;
        sc[n * 50 + m] = acc;
    }
    __syncthreads();

    if (tid < NN) {
        float* row = sc + tid * 50;
        float mx = -1e30f;
        #pragma unroll 7
        for (int m2 = 0; m2 < NN; ++m2) mx = fmaxf(mx, row[m2]);
        float s = 0.0f;
        #pragma unroll 7
        for (int m2 = 0; m2 < NN; ++m2) { float e = __expf(row[m2] - mx); row[m2] = e; s += e; }
        float inv = 1.0f / s;
        #pragma unroll 7
        for (int m2 = 0; m2 < NN; ++m2) row[m2] *= inv;
    }
    __syncthreads();

    for (int idx = tid; idx < NN * HD32; idx += 256) {
        int n = idx >> 5, d = idx & 31;
        const float* p = sc + n * 50;
        float acc = 0.0f;
        #pragma unroll 7
        for (int m2 = 0; m2 < NN; ++m2) acc += p[m2] * vs[m2 * HD32 + d];
        g_obuf[((size_t)(bn * NN + n)) * CC + h * HD32 + d] = acc;
    }
}

// ---------------- launch ----------------
extern "C" void kernel_launch(void* const* d_in, const int* in_sizes, int n_in,
                              void* d_out, int out_size) {
    const float* x       = (const float*)d_in[0];
    // d_in[1] = saliency_gt (unused)
    const float* norm1_w = (const float*)d_in[2];
    const float* norm1_b = (const float*)d_in[3];
    const float* qkv_w   = (const float*)d_in[4];
    const float* qkv_b   = (const float*)d_in[5];
    const float* rpb     = (const float*)d_in[6];
    const float* proj_w  = (const float*)d_in[7];
    const float* proj_b  = (const float*)d_in[8];
    const float* norm2_w = (const float*)d_in[9];
    const float* norm2_b = (const float*)d_in[10];
    const float* fc1_w   = (const float*)d_in[11];
    const float* fc1_b   = (const float*)d_in[12];
    const float* fc2_w   = (const float*)d_in[13];
    const float* fc2_b   = (const float*)d_in[14];
    float* out = (float*)d_out;

    const int SMEM = 2 * 64 * ROWSTRIDE * 4;  // 71680 bytes
    cudaFuncSetAttribute(gemm_kernel<128, 0>, cudaFuncAttributeMaxDynamicSharedMemorySize, SMEM);
    cudaFuncSetAttribute(gemm_kernel<128, 1>, cudaFuncAttributeMaxDynamicSharedMemorySize, SMEM);
    cudaFuncSetAttribute(gemm_kernel<128, 2>, cudaFuncAttributeMaxDynamicSharedMemorySize, SMEM);
    cudaFuncSetAttribute(gemm_kernel<512, 3>, cudaFuncAttributeMaxDynamicSharedMemorySize, SMEM);

    // 1) LN1 + shift + window partition
    ln1_gather_kernel<<<MROWS / 8, 256>>>(x, norm1_w, norm1_b);
    // 2) QKV projection (M=100352, K=128, OUT=384)
    gemm_kernel<128, 0><<<dim3(MROWS / 64, 6), 256, SMEM>>>(qkv_w, qkv_b, nullptr, nullptr);
    // 3) windowed attention
    attn_kernel<<<dim3(BB * NW, NH4), 256>>>(rpb);
    // 4) output projection + un-shift + residual
    gemm_kernel<128, 1><<<dim3(MROWS / 64, 2), 256, SMEM>>>(proj_w, proj_b, x, nullptr);
    // 5) LN2
    ln2_kernel<<<MROWS / 8, 256>>>(norm2_w, norm2_b);
    // 6) fc1 + gelu (OUT=512)
    gemm_kernel<128, 2><<<dim3(MROWS / 64, 8), 256, SMEM>>>(fc1_w, fc1_b, nullptr, nullptr);
    // 7) fc2 + residual (K=512, OUT=128)
    gemm_kernel<512, 3><<<dim3(MROWS / 64, 2), 256, SMEM>>>(fc2_w, fc2_b, nullptr, out);
}

// round 3
// speedup vs baseline: 2.6751x; 2.6751x over previous
#include <cuda_runtime.h>
#include <math.h>
#include <cstdint>

// ---------------- problem constants ----------------
#define HH     112
#define WW     112
#define CC     128
#define SHIFT3 3
#define NH4    4
#define BB     8
#define HID    512
#define NN     49
#define HD32   32
#define NW     256
#define LTOK   (HH*WW)      // 12544
#define MROWS  (BB*NW*NN)   // 100352 = 784*128
#define SCALEF 0.17677669529663687f

// ---------------- scratch ----------------
__device__ float g_xw  [MROWS*CC];
__device__ float g_q   [MROWS*CC];
__device__ float g_k   [MROWS*CC];
__device__ float g_v   [MROWS*CC];
__device__ float g_obuf[MROWS*CC];
__device__ float g_xres[MROWS*CC];
__device__ float g_y   [MROWS*CC];
__device__ float g_h1  [MROWS*HID];

__device__ __forceinline__ uint32_t tf32_rna(float x) {
    uint32_t u;
    asm("cvt.rna.tf32.f32 %0, %1;" : "=r"(u) : "f"(x));
    return u;
}

__device__ __forceinline__ void mma_tf32(float& c0, float& c1, float& c2, float& c3,
                                         uint32_t a0, uint32_t a1, uint32_t a2, uint32_t a3,
                                         uint32_t b0, uint32_t b1) {
    asm volatile("mma.sync.aligned.m16n8k8.row.col.f32.tf32.tf32.f32 "
                 "{%0,%1,%2,%3}, {%4,%5,%6,%7}, {%8,%9}, {%0,%1,%2,%3};"
                 : "+f"(c0), "+f"(c1), "+f"(c2), "+f"(c3)
                 : "r"(a0), "r"(a1), "r"(a2), "r"(a3), "r"(b0), "r"(b1));
}

// ---------------- LN1 + roll(-3,-3) + window partition ----------------
__global__ void ln1_gather_kernel(const float* __restrict__ x,
                                  const float* __restrict__ w,
                                  const float* __restrict__ b) {
    int row  = blockIdx.x * 8 + (threadIdx.x >> 5);
    int lane = threadIdx.x & 31;
    int bn = row / NN, n = row - bn * NN;
    int bi = bn >> 8, win = bn & 255;
    int wi = win >> 4, wj = win & 15;
    int r = n / 7, c = n - r * 7;
    int i = wi * 7 + r, j = wj * 7 + c;
    int si = i + SHIFT3; if (si >= HH) si -= HH;
    int sj = j + SHIFT3; if (sj >= WW) sj -= WW;
    const float4* src = (const float4*)(x + ((size_t)bi * LTOK + si * WW + sj) * CC);
    float4 v = src[lane];
    float s = v.x + v.y + v.z + v.w;
    #pragma unroll
    for (int o = 16; o; o >>= 1) s += __shfl_xor_sync(0xffffffffu, s, o);
    float mean = s * (1.0f / 128.0f);
    float dx = v.x - mean, dy = v.y - mean, dz = v.z - mean, dw = v.w - mean;
    float q = dx*dx + dy*dy + dz*dz + dw*dw;
    #pragma unroll
    for (int o = 16; o; o >>= 1) q += __shfl_xor_sync(0xffffffffu, q, o);
    float inv = rsqrtf(q * (1.0f / 128.0f) + 1e-5f);
    float4 wv = ((const float4*)w)[lane];
    float4 bv = ((const float4*)b)[lane];
    float4 o4;
    o4.x = dx * inv * wv.x + bv.x;
    o4.y = dy * inv * wv.y + bv.y;
    o4.z = dz * inv * wv.z + bv.z;
    o4.w = dw * inv * wv.w + bv.w;
    ((float4*)(g_xw + (size_t)row * CC))[lane] = o4;
}

// ---------------- LN2 ----------------
__global__ void ln2_kernel(const float* __restrict__ w, const float* __restrict__ b) {
    int row  = blockIdx.x * 8 + (threadIdx.x >> 5);
    int lane = threadIdx.x & 31;
    float4 v = ((const float4*)(g_xres + (size_t)row * CC))[lane];
    float s = v.x + v.y + v.z + v.w;
    #pragma unroll
    for (int o = 16; o; o >>= 1) s += __shfl_xor_sync(0xffffffffu, s, o);
    float mean = s * (1.0f / 128.0f);
    float dx = v.x - mean, dy = v.y - mean, dz = v.z - mean, dw = v.w - mean;
    float q = dx*dx + dy*dy + dz*dz + dw*dw;
    #pragma unroll
    for (int o = 16; o; o >>= 1) q += __shfl_xor_sync(0xffffffffu, q, o);
    float inv = rsqrtf(q * (1.0f / 128.0f) + 1e-5f);
    float4 wv = ((const float4*)w)[lane];
    float4 bv = ((const float4*)b)[lane];
    float4 o4;
    o4.x = dx * inv * wv.x + bv.x;
    o4.y = dy * inv * wv.y + bv.y;
    o4.z = dz * inv * wv.z + bv.z;
    o4.w = dw * inv * wv.w + bv.w;
    ((float4*)(g_y + (size_t)row * CC))[lane] = o4;
}

// ---------------- tf32 mma.sync GEMM: C[m][o] = sum_k A[m][k]*W[o][k] ----------------
// CTA tile 128x128, 8 warps (4M x 2N), warp tile 32x64 = 2x8 m16n8k8 frags.
// K staged in 64-float chunks, smem stride 68 (conflict-free frag loads).
// MODE 0: A=g_xw,  epilogue split+scale -> g_q/g_k/g_v (bn,h,n,d)
// MODE 1: A=g_obuf,epilogue +proj_b, un-shift scatter + residual -> g_xres
// MODE 2: A=g_y,   epilogue +fc1_b, exact gelu -> g_h1
// MODE 3: A=g_h1,  K=512, epilogue +fc2_b + g_xres -> out
#define CHK   64
#define SST   68
#define SMTOT (2 * 128 * SST * 4)   // 69632 bytes

template<int KDIM, int MODE>
__global__ void __launch_bounds__(256, 2)
gemm_mma(const float* __restrict__ W, const float* __restrict__ bias,
         const float* __restrict__ xin, float* __restrict__ outp) {
    extern __shared__ float sm[];
    float* As = sm;                 // 128 x SST
    float* Bs = sm + 128 * SST;     // 128 x SST
    const float* A = (MODE == 0) ? g_xw : (MODE == 1) ? g_obuf : (MODE == 2) ? g_y : g_h1;

    const int m0 = blockIdx.x * 128;
    const int o0 = blockIdx.y * 128;
    const int tid  = threadIdx.x;
    const int wid  = tid >> 5;
    const int lane = tid & 31;
    const int g = lane >> 2;        // group 0..7
    const int t = lane & 3;         // thread-in-group
    const int wm = (wid >> 1) * 32; // warp m offset within tile
    const int wn = (wid & 1) * 64;  // warp n offset within tile

    float acc[2][8][4];
    #pragma unroll
    for (int mi = 0; mi < 2; ++mi)
        #pragma unroll
        for (int ni = 0; ni < 8; ++ni)
            #pragma unroll
            for (int q = 0; q < 4; ++q) acc[mi][ni][q] = 0.0f;

    #pragma unroll 1
    for (int k0 = 0; k0 < KDIM; k0 += CHK) {
        // stage A/B 64-k chunks, tf32-rounded
        #pragma unroll
        for (int it = 0; it < 8; ++it) {
            int idx = tid + it * 256;
            int r = idx >> 4, c4 = idx & 15;
            float4 av = *(const float4*)(A + (size_t)(m0 + r) * KDIM + k0 + c4 * 4);
            uint4 au;
            au.x = tf32_rna(av.x); au.y = tf32_rna(av.y);
            au.z = tf32_rna(av.z); au.w = tf32_rna(av.w);
            *(uint4*)(As + r * SST + c4 * 4) = au;
            float4 wv = *(const float4*)(W + (size_t)(o0 + r) * KDIM + k0 + c4 * 4);
            uint4 wu;
            wu.x = tf32_rna(wv.x); wu.y = tf32_rna(wv.y);
            wu.z = tf32_rna(wv.z); wu.w = tf32_rna(wv.w);
            *(uint4*)(Bs + r * SST + c4 * 4) = wu;
        }
        __syncthreads();

        #pragma unroll
        for (int kk = 0; kk < CHK; kk += 8) {
            uint32_t af[2][4];
            #pragma unroll
            for (int mi = 0; mi < 2; ++mi) {
                const uint32_t* Ap = (const uint32_t*)(As + (wm + mi * 16) * SST + kk);
                af[mi][0] = Ap[(g)     * SST + t];
                af[mi][1] = Ap[(g + 8) * SST + t];
                af[mi][2] = Ap[(g)     * SST + t + 4];
                af[mi][3] = Ap[(g + 8) * SST + t + 4];
            }
            uint32_t bf[8][2];
            #pragma unroll
            for (int ni = 0; ni < 8; ++ni) {
                const uint32_t* Bp = (const uint32_t*)(Bs + (wn + ni * 8 + g) * SST + kk);
                bf[ni][0] = Bp[t];
                bf[ni][1] = Bp[t + 4];
            }
            #pragma unroll
            for (int mi = 0; mi < 2; ++mi)
                #pragma unroll
                for (int ni = 0; ni < 8; ++ni)
                    mma_tf32(acc[mi][ni][0], acc[mi][ni][1], acc[mi][ni][2], acc[mi][ni][3],
                             af[mi][0], af[mi][1], af[mi][2], af[mi][3],
                             bf[ni][0], bf[ni][1]);
        }
        __syncthreads();
    }

    // ---------------- epilogue ----------------
    // thread owns rows {wm+mi*16+g, +8}, cols {wn+ni*8+2t, +1}
    #pragma unroll
    for (int mi = 0; mi < 2; ++mi) {
        #pragma unroll
        for (int half = 0; half < 2; ++half) {
            int m = m0 + wm + mi * 16 + g + half * 8;
            if (MODE == 0) {
                int bn = m / NN, n = m - bn * NN;
                float* dst = (blockIdx.y == 0) ? g_q : (blockIdx.y == 1) ? g_k : g_v;
                float scl = (blockIdx.y == 0) ? SCALEF : 1.0f;
                #pragma unroll
                for (int ni = 0; ni < 8; ++ni) {
                    int ol = wn + ni * 8 + 2 * t;
                    int hh = ol >> 5, dd = ol & 31;
                    float2 v;
                    v.x = (acc[mi][ni][half*2+0] + bias[o0 + ol])     * scl;
                    v.y = (acc[mi][ni][half*2+1] + bias[o0 + ol + 1]) * scl;
                    *(float2*)(dst + (size_t)(bn * NH4 + hh) * (NN * HD32) + n * HD32 + dd) = v;
                }
            } else if (MODE == 1) {
                int bn = m / NN, n = m - bn * NN;
                int bi = bn >> 8, win = bn & 255;
                int wi = win >> 4, wj = win & 15;
                int r = n / 7, cq = n - r * 7;
                int ii = wi * 7 + r + SHIFT3;  if (ii >= HH) ii -= HH;
                int jj = wj * 7 + cq + SHIFT3; if (jj >= WW) jj -= WW;
                size_t tok = (size_t)bi * LTOK + ii * WW + jj;
                #pragma unroll
                for (int ni = 0; ni < 8; ++ni) {
                    int ol = wn + ni * 8 + 2 * t;
                    float2 xr = *(const float2*)(xin + tok * CC + ol);
                    float2 v;
                    v.x = acc[mi][ni][half*2+0] + bias[ol]     + xr.x;
                    v.y = acc[mi][ni][half*2+1] + bias[ol + 1] + xr.y;
                    *(float2*)(g_xres + tok * CC + ol) = v;
                }
            } else if (MODE == 2) {
                #pragma unroll
                for (int ni = 0; ni < 8; ++ni) {
                    int ol = wn + ni * 8 + 2 * t;
                    float a = acc[mi][ni][half*2+0] + bias[o0 + ol];
                    float b = acc[mi][ni][half*2+1] + bias[o0 + ol + 1];
                    float2 v;
                    v.x = 0.5f * a * (1.0f + erff(a * 0.70710678118654752f));
                    v.y = 0.5f * b * (1.0f + erff(b * 0.70710678118654752f));
                    *(float2*)(g_h1 + (size_t)m * HID + o0 + ol) = v;
                }
            } else {
                #pragma unroll
                for (int ni = 0; ni < 8; ++ni) {
                    int ol = wn + ni * 8 + 2 * t;
                    float2 xr = *(const float2*)(g_xres + (size_t)m * CC + ol);
                    float2 v;
                    v.x = acc[mi][ni][half*2+0] + bias[ol]     + xr.x;
                    v.y = acc[mi][ni][half*2+1] + bias[ol + 1] + xr.y;
                    *(float2*)(outp + (size_t)m * CC + ol) = v;
                }
            }
        }
    }
}

// ---------------- windowed attention ----------------
__device__ __forceinline__ int regionf(int i) { return (i < 105) ? 0 : ((i < 109) ? 1 : 2); }

__global__ void attn_kernel(const float* __restrict__ rpb) {
    int bn = blockIdx.x;
    int h  = blockIdx.y;
    __shared__ float qs[NN * HD32];
    __shared__ float ks[NN * HD32];
    __shared__ float vs[NN * HD32];
    __shared__ float sc[NN * 50];
    int tid = threadIdx.x;

    size_t base = ((size_t)(bn * NH4 + h)) * NN * HD32;
    for (int idx = tid; idx < (NN * HD32) / 4; idx += 256) {
        ((float4*)qs)[idx] = ((const float4*)(g_q + base))[idx];
        ((float4*)ks)[idx] = ((const float4*)(g_k + base))[idx];
        ((float4*)vs)[idx] = ((const float4*)(g_v + base))[idx];
    }
    __syncthreads();

    int win = bn & 255, wi = win >> 4, wj = win & 15;
    for (int idx = tid; idx < NN * NN; idx += 256) {
        int n = idx / NN, m = idx - n * NN;
        const float4* qp = (const float4*)(qs + n * HD32);
        const float4* kp = (const float4*)(ks + m * HD32);
        float acc = 0.0f;
        #pragma unroll
        for (int d = 0; d < 8; ++d) {
            float4 a = qp[d], b = kp[d];
            acc += a.x * b.x + a.y * b.y + a.z * b.z + a.w * b.w;
        }
        int r1 = n / 7, c1 = n - r1 * 7;
        int r2 = m / 7, c2 = m - r2 * 7;
        int bidx = (r1 - r2 + 6) * 13 + (c1 - c2 + 6);
        acc += rpb[bidx * NH4 + h];
        int reg1 = regionf(wi * 7 + r1) * 3 + regionf(wj * 7 + c1);
        int reg2 = regionf(wi * 7 + r2) * 3 + regionf(wj * 7 + c2);
        if (reg1 != reg2) acc -= 100.0f;
        sc[n * 50 + m] = acc;
    }
    __syncthreads();

    if (tid < NN) {
        float* row = sc + tid * 50;
        float mx = -1e30f;
        #pragma unroll 7
        for (int m2 = 0; m2 < NN; ++m2) mx = fmaxf(mx, row[m2]);
        float s = 0.0f;
        #pragma unroll 7
        for (int m2 = 0; m2 < NN; ++m2) { float e = __expf(row[m2] - mx); row[m2] = e; s += e; }
        float inv = 1.0f / s;
        #pragma unroll 7
        for (int m2 = 0; m2 < NN; ++m2) row[m2] *= inv;
    }
    __syncthreads();

    for (int idx = tid; idx < NN * HD32; idx += 256) {
        int n = idx >> 5, d = idx & 31;
        const float* p = sc + n * 50;
        float acc = 0.0f;
        #pragma unroll 7
        for (int m2 = 0; m2 < NN; ++m2) acc += p[m2] * vs[m2 * HD32 + d];
        g_obuf[((size_t)(bn * NN + n)) * CC + h * HD32 + d] = acc;
    }
}

// ---------------- launch ----------------
extern "C" void kernel_launch(void* const* d_in, const int* in_sizes, int n_in,
                              void* d_out, int out_size) {
    const float* x       = (const float*)d_in[0];
    const float* norm1_w = (const float*)d_in[2];
    const float* norm1_b = (const float*)d_in[3];
    const float* qkv_w   = (const float*)d_in[4];
    const float* qkv_b   = (const float*)d_in[5];
    const float* rpb     = (const float*)d_in[6];
    const float* proj_w  = (const float*)d_in[7];
    const float* proj_b  = (const float*)d_in[8];
    const float* norm2_w = (const float*)d_in[9];
    const float* norm2_b = (const float*)d_in[10];
    const float* fc1_w   = (const float*)d_in[11];
    const float* fc1_b   = (const float*)d_in[12];
    const float* fc2_w   = (const float*)d_in[13];
    const float* fc2_b   = (const float*)d_in[14];
    float* out = (float*)d_out;

    cudaFuncSetAttribute(gemm_mma<128, 0>, cudaFuncAttributeMaxDynamicSharedMemorySize, SMTOT);
    cudaFuncSetAttribute(gemm_mma<128, 1>, cudaFuncAttributeMaxDynamicSharedMemorySize, SMTOT);
    cudaFuncSetAttribute(gemm_mma<128, 2>, cudaFuncAttributeMaxDynamicSharedMemorySize, SMTOT);
    cudaFuncSetAttribute(gemm_mma<512, 3>, cudaFuncAttributeMaxDynamicSharedMemorySize, SMTOT);

    ln1_gather_kernel<<<MROWS / 8, 256>>>(x, norm1_w, norm1_b);
    gemm_mma<128, 0><<<dim3(MROWS / 128, 3), 256, SMTOT>>>(qkv_w, qkv_b, nullptr, nullptr);
    attn_kernel<<<dim3(BB * NW, NH4), 256>>>(rpb);
    gemm_mma<128, 1><<<dim3(MROWS / 128, 1), 256, SMTOT>>>(proj_w, proj_b, x, nullptr);
    ln2_kernel<<<MROWS / 8, 256>>>(norm2_w, norm2_b);
    gemm_mma<128, 2><<<dim3(MROWS / 128, 4), 256, SMTOT>>>(fc1_w, fc1_b, nullptr, nullptr);
    gemm_mma<512, 3><<<dim3(MROWS / 128, 1), 256, SMTOT>>>(fc2_w, fc2_b, nullptr, out);
}

// round 5
// speedup vs baseline: 5.5811x; 2.0863x over previous
#include <cuda_runtime.h>
#include <cuda_bf16.h>
#include <math.h>
#include <cstdint>

// ---------------- problem constants ----------------
#define HH     112
#define WW     112
#define CC     128
#define SHIFT3 3
#define NH4    4
#define BB     8
#define HID    512
#define NN     49
#define HD32   32
#define NW     256
#define LTOK   (HH*WW)      // 12544
#define MROWS  (BB*NW*NN)   // 100352 = 784*128
#define SCALEF 0.17677669529663687f

// ---------------- scratch ----------------
__device__ __nv_bfloat16 g_xw_bf  [MROWS*CC];
__device__ __nv_bfloat16 g_obuf_bf[MROWS*CC];
__device__ __nv_bfloat16 g_y_bf   [MROWS*CC];
__device__ __nv_bfloat16 g_h1_bf  [MROWS*HID];
__device__ float g_q   [MROWS*CC];
__device__ float g_k   [MROWS*CC];
__device__ float g_v   [MROWS*CC];
__device__ float g_xres[MROWS*CC];
__device__ __nv_bfloat16 g_qkvw[3*CC*CC];
__device__ __nv_bfloat16 g_projw[CC*CC];
__device__ __nv_bfloat16 g_fc1w[HID*CC];
__device__ __nv_bfloat16 g_fc2w[CC*HID];

// ---------------- helpers ----------------
__device__ __forceinline__ uint32_t smem_u32(const void* p) {
    uint32_t a;
    asm("{ .reg .u64 t; cvta.to.shared.u64 t, %1; cvt.u32.u64 %0, t; }" : "=r"(a) : "l"(p));
    return a;
}
__device__ __forceinline__ uint32_t bf2_as_u32(__nv_bfloat162 v) {
    uint32_t u;
    asm("mov.b32 %0, %1;" : "=r"(u) : "r"(*(uint32_t*)&v));
    return u;
}
__device__ __forceinline__ uint32_t pack_bf2(float lo, float hi) {
    __nv_bfloat162 v = __floats2bfloat162_rn(lo, hi);
    return *(uint32_t*)&v;
}
__device__ __forceinline__ void mma_bf16(float& c0, float& c1, float& c2, float& c3,
                                         uint32_t a0, uint32_t a1, uint32_t a2, uint32_t a3,
                                         uint32_t b0, uint32_t b1) {
    asm volatile("mma.sync.aligned.m16n8k16.row.col.f32.bf16.bf16.f32 "
                 "{%0,%1,%2,%3}, {%4,%5,%6,%7}, {%8,%9}, {%0,%1,%2,%3};"
                 : "+f"(c0), "+f"(c1), "+f"(c2), "+f"(c3)
                 : "r"(a0), "r"(a1), "r"(a2), "r"(a3), "r"(b0), "r"(b1));
}
#define CP_ASYNC16(dst, src) \
    asm volatile("cp.async.cg.shared.global [%0], [%1], 16;" :: "r"(dst), "l"(src))
#define CP_COMMIT() asm volatile("cp.async.commit_group;" ::: "memory")
#define CP_WAIT0()  asm volatile("cp.async.wait_group 0;" ::: "memory")
#define CP_WAIT1()  asm volatile("cp.async.wait_group 1;" ::: "memory")

// ---------------- fp32 -> bf16 weight conversion ----------------
__global__ void cvt_kernel(const float* __restrict__ s, __nv_bfloat16* __restrict__ d, int n) {
    int i = (blockIdx.x * 256 + threadIdx.x) * 4;
    if (i < n) {
        float4 v = *(const float4*)(s + i);
        __nv_bfloat162 p0 = __floats2bfloat162_rn(v.x, v.y);
        __nv_bfloat162 p1 = __floats2bfloat162_rn(v.z, v.w);
        *(__nv_bfloat162*)(d + i)     = p0;
        *(__nv_bfloat162*)(d + i + 2) = p1;
    }
}

// ---------------- LN1 + roll(-3,-3) + window partition -> bf16 ----------------
__global__ void ln1_gather_kernel(const float* __restrict__ x,
                                  const float* __restrict__ w,
                                  const float* __restrict__ b) {
    int row  = blockIdx.x * 8 + (threadIdx.x >> 5);
    int lane = threadIdx.x & 31;
    int bn = row / NN, n = row - bn * NN;
    int bi = bn >> 8, win = bn & 255;
    int wi = win >> 4, wj = win & 15;
    int r = n / 7, c = n - r * 7;
    int si = wi * 7 + r + SHIFT3; if (si >= HH) si -= HH;
    int sj = wj * 7 + c + SHIFT3; if (sj >= WW) sj -= WW;
    const float4* src = (const float4*)(x + ((size_t)bi * LTOK + si * WW + sj) * CC);
    float4 v = src[lane];
    float s = v.x + v.y + v.z + v.w;
    #pragma unroll
    for (int o = 16; o; o >>= 1) s += __shfl_xor_sync(0xffffffffu, s, o);
    float mean = s * (1.0f / 128.0f);
    float dx = v.x - mean, dy = v.y - mean, dz = v.z - mean, dw = v.w - mean;
    float q = dx*dx + dy*dy + dz*dz + dw*dw;
    #pragma unroll
    for (int o = 16; o; o >>= 1) q += __shfl_xor_sync(0xffffffffu, q, o);
    float inv = rsqrtf(q * (1.0f / 128.0f) + 1e-5f);
    float4 wv = ((const float4*)w)[lane];
    float4 bv = ((const float4*)b)[lane];
    uint2 pk;
    pk.x = pack_bf2(dx * inv * wv.x + bv.x, dy * inv * wv.y + bv.y);
    pk.y = pack_bf2(dz * inv * wv.z + bv.z, dw * inv * wv.w + bv.w);
    *(uint2*)(g_xw_bf + (size_t)row * CC + lane * 4) = pk;
}

// ---------------- LN2 -> bf16 ----------------
__global__ void ln2_kernel(const float* __restrict__ w, const float* __restrict__ b) {
    int row  = blockIdx.x * 8 + (threadIdx.x >> 5);
    int lane = threadIdx.x & 31;
    float4 v = ((const float4*)(g_xres + (size_t)row * CC))[lane];
    float s = v.x + v.y + v.z + v.w;
    #pragma unroll
    for (int o = 16; o; o >>= 1) s += __shfl_xor_sync(0xffffffffu, s, o);
    float mean = s * (1.0f / 128.0f);
    float dx = v.x - mean, dy = v.y - mean, dz = v.z - mean, dw = v.w - mean;
    float q = dx*dx + dy*dy + dz*dz + dw*dw;
    #pragma unroll
    for (int o = 16; o; o >>= 1) q += __shfl_xor_sync(0xffffffffu, q, o);
    float inv = rsqrtf(q * (1.0f / 128.0f) + 1e-5f);
    float4 wv = ((const float4*)w)[lane];
    float4 bv = ((const float4*)b)[lane];
    uint2 pk;
    pk.x = pack_bf2(dx * inv * wv.x + bv.x, dy * inv * wv.y + bv.y);
    pk.y = pack_bf2(dz * inv * wv.z + bv.z, dw * inv * wv.w + bv.w);
    *(uint2*)(g_y_bf + (size_t)row * CC + lane * 4) = pk;
}

// ---------------- bf16 mma GEMM: C[m][o] = sum_k A[m][k]*W[o][k] ----------------
// CTA tile 128x128, 8 warps (4m x 2n), warp 32x64 = 2x8 m16n8k16 frags.
// K chunked by 64, cp.async double-buffered.
// smem per buffer: A 128 rows x 144B + B same; stride 36 uint32 (conflict-free frags).
#define SMTOT 73728

template<int KDIM, int MODE>
__global__ void __launch_bounds__(256, 2)
gemm_bf(const __nv_bfloat16* __restrict__ A, const __nv_bfloat16* __restrict__ Wb,
        const float* __restrict__ bias, const float* __restrict__ xin,
        float* __restrict__ outp) {
    extern __shared__ char smem[];
    const uint32_t sbase = smem_u32(smem);
    const uint32_t* smu = (const uint32_t*)smem;

    const int m0 = blockIdx.x * 128;
    const int o0 = blockIdx.y * 128;
    const int tid  = threadIdx.x;
    const int wid  = tid >> 5;
    const int lane = tid & 31;
    const int g = lane >> 2;
    const int t = lane & 3;
    const int wm = (wid >> 1) * 32;
    const int wn = (wid & 1) * 64;
    const int NC = KDIM / 64;

    float acc[2][8][4];
    #pragma unroll
    for (int mi = 0; mi < 2; ++mi)
        #pragma unroll
        for (int ni = 0; ni < 8; ++ni)
            #pragma unroll
            for (int q = 0; q < 4; ++q) acc[mi][ni][q] = 0.0f;

    // prologue stage chunk 0
    {
        #pragma unroll
        for (int it = 0; it < 4; ++it) {
            int idx = tid + it * 256;
            int r = idx >> 3, cc = idx & 7;
            uint32_t da = sbase + r * 144 + cc * 16;
            CP_ASYNC16(da, A + (size_t)(m0 + r) * KDIM + cc * 8);
            CP_ASYNC16(da + 18432, Wb + (size_t)(o0 + r) * KDIM + cc * 8);
        }
        CP_COMMIT();
    }

    #pragma unroll 1
    for (int c = 0; c < NC; ++c) {
        if (c + 1 < NC) {
            int k0 = (c + 1) * 64;
            int sel = (c + 1) & 1;
            #pragma unroll
            for (int it = 0; it < 4; ++it) {
                int idx = tid + it * 256;
                int r = idx >> 3, cc = idx & 7;
                uint32_t da = sbase + sel * 36864 + r * 144 + cc * 16;
                CP_ASYNC16(da, A + (size_t)(m0 + r) * KDIM + k0 + cc * 8);
                CP_ASYNC16(da + 18432, Wb + (size_t)(o0 + r) * KDIM + k0 + cc * 8);
            }
            CP_COMMIT();
            CP_WAIT1();
        } else {
            CP_WAIT0();
        }
        __syncthreads();

        const uint32_t* S = smu + (c & 1) * 9216;
        #pragma unroll
        for (int kk2 = 0; kk2 < 32; kk2 += 8) {
            uint32_t af[2][4];
            #pragma unroll
            for (int mi = 0; mi < 2; ++mi) {
                const uint32_t* Ap = S + (wm + mi * 16) * 36 + kk2;
                af[mi][0] = Ap[g * 36 + t];
                af[mi][1] = Ap[(g + 8) * 36 + t];
                af[mi][2] = Ap[g * 36 + t + 4];
                af[mi][3] = Ap[(g + 8) * 36 + t + 4];
            }
            uint32_t bf[8][2];
            #pragma unroll
            for (int ni = 0; ni < 8; ++ni) {
                const uint32_t* Bp = S + 4608 + (wn + ni * 8 + g) * 36 + kk2;
                bf[ni][0] = Bp[t];
                bf[ni][1] = Bp[t + 4];
            }
            #pragma unroll
            for (int mi = 0; mi < 2; ++mi)
                #pragma unroll
                for (int ni = 0; ni < 8; ++ni)
                    mma_bf16(acc[mi][ni][0], acc[mi][ni][1], acc[mi][ni][2], acc[mi][ni][3],
                             af[mi][0], af[mi][1], af[mi][2], af[mi][3],
                             bf[ni][0], bf[ni][1]);
        }
        __syncthreads();
    }

    // ---------------- epilogue (thread owns rows wm+mi*16+g(+8), cols wn+ni*8+2t(+1)) -----
    #pragma unroll
    for (int mi = 0; mi < 2; ++mi) {
        #pragma unroll
        for (int half = 0; half < 2; ++half) {
            int m = m0 + wm + mi * 16 + g + half * 8;
            if (MODE == 0) {
                int bn = m / NN, n = m - bn * NN;
                float* dst = (blockIdx.y == 0) ? g_q : (blockIdx.y == 1) ? g_k : g_v;
                float scl = (blockIdx.y == 0) ? SCALEF : 1.0f;
                #pragma unroll
                for (int ni = 0; ni < 8; ++ni) {
                    int ol = wn + ni * 8 + 2 * t;
                    int hh = ol >> 5, dd = ol & 31;
                    float2 v;
                    v.x = (acc[mi][ni][half*2+0] + bias[o0 + ol])     * scl;
                    v.y = (acc[mi][ni][half*2+1] + bias[o0 + ol + 1]) * scl;
                    *(float2*)(dst + (size_t)(bn * NH4 + hh) * (NN * HD32) + n * HD32 + dd) = v;
                }
            } else if (MODE == 1) {
                int bn = m / NN, n = m - bn * NN;
                int bi = bn >> 8, win = bn & 255;
                int wi = win >> 4, wj = win & 15;
                int r = n / 7, cq = n - r * 7;
                int ii = wi * 7 + r + SHIFT3;  if (ii >= HH) ii -= HH;
                int jj = wj * 7 + cq + SHIFT3; if (jj >= WW) jj -= WW;
                size_t tok = (size_t)bi * LTOK + ii * WW + jj;
                #pragma unroll
                for (int ni = 0; ni < 8; ++ni) {
                    int ol = wn + ni * 8 + 2 * t;
                    float2 xr = *(const float2*)(xin + tok * CC + ol);
                    float2 v;
                    v.x = acc[mi][ni][half*2+0] + bias[ol]     + xr.x;
                    v.y = acc[mi][ni][half*2+1] + bias[ol + 1] + xr.y;
                    *(float2*)(g_xres + tok * CC + ol) = v;
                }
            } else if (MODE == 2) {
                #pragma unroll
                for (int ni = 0; ni < 8; ++ni) {
                    int ol = wn + ni * 8 + 2 * t;
                    float a = acc[mi][ni][half*2+0] + bias[o0 + ol];
                    float b = acc[mi][ni][half*2+1] + bias[o0 + ol + 1];
                    float ga = 0.5f * a * (1.0f + erff(a * 0.70710678118654752f));
                    float gb = 0.5f * b * (1.0f + erff(b * 0.70710678118654752f));
                    *(uint32_t*)(g_h1_bf + (size_t)m * HID + o0 + ol) = pack_bf2(ga, gb);
                }
            } else {
                #pragma unroll
                for (int ni = 0; ni < 8; ++ni) {
                    int ol = wn + ni * 8 + 2 * t;
                    float2 xr = *(const float2*)(g_xres + (size_t)m * CC + ol);
                    float2 v;
                    v.x = acc[mi][ni][half*2+0] + bias[ol]     + xr.x;
                    v.y = acc[mi][ni][half*2+1] + bias[ol + 1] + xr.y;
                    *(float2*)(outp + (size_t)m * CC + ol) = v;
                }
            }
        }
    }
}

// ---------------- windowed attention (register-tiled) ----------------
__device__ __forceinline__ int regionf(int i) { return (i < 105) ? 0 : ((i < 109) ? 1 : 2); }

__global__ void __launch_bounds__(128)
attn_kernel(const float* __restrict__ rpb) {
    int bn = blockIdx.x;
    int h  = blockIdx.y;
    __shared__ float qs[52 * HD32];
    __shared__ float ks[52 * HD32];
    __shared__ float vs[NN * HD32];
    __shared__ float sc[50 * 52];
    __shared__ float bs[169];
    int tid = threadIdx.x;

    size_t base = ((size_t)(bn * NH4 + h)) * NN * HD32;
    for (int idx = tid; idx < 392; idx += 128) {
        ((float4*)qs)[idx] = ((const float4*)(g_q + base))[idx];
        ((float4*)ks)[idx] = ((const float4*)(g_k + base))[idx];
        ((float4*)vs)[idx] = ((const float4*)(g_v + base))[idx];
    }
    for (int i = tid; i < 169; i += 128) bs[i] = rpb[i * NH4 + h];
    __syncthreads();

    int win = bn & 255, wi = win >> 4, wj = win & 15;

    // QK^T + bias + mask, 4x4 register tiles (13x13 = 169 tiles)
    for (int tl = tid; tl < 169; tl += 128) {
        int tn = tl / 13, tm = tl - tn * 13;
        int n0 = tn * 4, m0 = tm * 4;
        float acc[4][4];
        #pragma unroll
        for (int i = 0; i < 4; ++i)
            #pragma unroll
            for (int j = 0; j < 4; ++j) acc[i][j] = 0.0f;
        #pragma unroll
        for (int kc = 0; kc < 32; kc += 8) {
            float4 qa[4][2], ka[4][2];
            #pragma unroll
            for (int i = 0; i < 4; ++i) {
                qa[i][0] = *(const float4*)(qs + (n0 + i) * HD32 + kc);
                qa[i][1] = *(const float4*)(qs + (n0 + i) * HD32 + kc + 4);
                ka[i][0] = *(const float4*)(ks + (m0 + i) * HD32 + kc);
                ka[i][1] = *(const float4*)(ks + (m0 + i) * HD32 + kc + 4);
            }
            #pragma unroll
            for (int i = 0; i < 4; ++i)
                #pragma unroll
                for (int j = 0; j < 4; ++j) {
                    acc[i][j] += qa[i][0].x * ka[j][0].x + qa[i][0].y * ka[j][0].y
                               + qa[i][0].z * ka[j][0].z + qa[i][0].w * ka[j][0].w
                               + qa[i][1].x * ka[j][1].x + qa[i][1].y * ka[j][1].y
                               + qa[i][1].z * ka[j][1].z + qa[i][1].w * ka[j][1].w;
                }
        }
        #pragma unroll
        for (int i = 0; i < 4; ++i) {
            int n = n0 + i;
            if (n >= NN) break;
            int r1 = n / 7, c1 = n - r1 * 7;
            int reg1 = regionf(wi * 7 + r1) * 3 + regionf(wj * 7 + c1);
            #pragma unroll
            for (int j = 0; j < 4; ++j) {
                int m = m0 + j;
                if (m >= NN) continue;
                int r2 = m / 7, c2 = m - r2 * 7;
                float v = acc[i][j] + bs[(r1 - r2 + 6) * 13 + (c1 - c2 + 6)];
                int reg2 = regionf(wi * 7 + r2) * 3 + regionf(wj * 7 + c2);
                if (reg1 != reg2) v -= 100.0f;
                sc[n * 52 + m] = v;
            }
        }
    }
    __syncthreads();

    // softmax (thread per row)
    if (tid < NN) {
        float* row = sc + tid * 52;
        float mx = -1e30f;
        #pragma unroll 7
        for (int m2 = 0; m2 < NN; ++m2) mx = fmaxf(mx, row[m2]);
        float s = 0.0f;
        #pragma unroll 7
        for (int m2 = 0; m2 < NN; ++m2) { float e = __expf(row[m2] - mx); row[m2] = e; s += e; }
        float inv = 1.0f / s;
        #pragma unroll 7
        for (int m2 = 0; m2 < NN; ++m2) row[m2] *= inv;
    }
    __syncthreads();

    // P @ V with 2n x 8d tiling (25 n-pairs x 4 d-groups = 100 units), bf16 output
    if (tid < 100) {
        int n0 = (tid >> 2) * 2;
        int d0 = (tid & 3) * 8;
        float a0[8], a1[8];
        #pragma unroll
        for (int i = 0; i < 8; ++i) { a0[i] = 0.0f; a1[i] = 0.0f; }
        const float* p0 = sc + n0 * 52;
        const float* p1 = sc + (n0 + 1) * 52;
        #pragma unroll 7
        for (int m2 = 0; m2 < NN; ++m2) {
            float w0 = p0[m2], w1 = p1[m2];
            float4 va = *(const float4*)(vs + m2 * HD32 + d0);
            float4 vb = *(const float4*)(vs + m2 * HD32 + d0 + 4);
            a0[0] += w0 * va.x; a0[1] += w0 * va.y; a0[2] += w0 * va.z; a0[3] += w0 * va.w;
            a0[4] += w0 * vb.x; a0[5] += w0 * vb.y; a0[6] += w0 * vb.z; a0[7] += w0 * vb.w;
            a1[0] += w1 * va.x; a1[1] += w1 * va.y; a1[2] += w1 * va.z; a1[3] += w1 * va.w;
            a1[4] += w1 * vb.x; a1[5] += w1 * vb.y; a1[6] += w1 * vb.z; a1[7] += w1 * vb.w;
        }
        __nv_bfloat16* o = g_obuf_bf + ((size_t)(bn * NN + n0)) * CC + h * HD32 + d0;
        uint4 pk;
        pk.x = pack_bf2(a0[0], a0[1]);
        pk.y = pack_bf2(a0[2], a0[3]);
        pk.z = pack_bf2(a0[4], a0[5]);
        pk.w = pack_bf2(a0[6], a0[7]);
        *(uint4*)o = pk;
        if (n0 + 1 < NN) {
            pk.x = pack_bf2(a1[0], a1[1]);
            pk.y = pack_bf2(a1[2], a1[3]);
            pk.z = pack_bf2(a1[4], a1[5]);
            pk.w = pack_bf2(a1[6], a1[7]);
            *(uint4*)(o + CC) = pk;
        }
    }
}

// ---------------- launch ----------------
extern "C" void kernel_launch(void* const* d_in, const int* in_sizes, int n_in,
                              void* d_out, int out_size) {
    const float* x       = (const float*)d_in[0];
    const float* norm1_w = (const float*)d_in[2];
    const float* norm1_b = (const float*)d_in[3];
    const float* qkv_w   = (const float*)d_in[4];
    const float* qkv_b   = (const float*)d_in[5];
    const float* rpb     = (const float*)d_in[6];
    const float* proj_w  = (const float*)d_in[7];
    const float* proj_b  = (const float*)d_in[8];
    const float* norm2_w = (const float*)d_in[9];
    const float* norm2_b = (const float*)d_in[10];
    const float* fc1_w   = (const float*)d_in[11];
    const float* fc1_b   = (const float*)d_in[12];
    const float* fc2_w   = (const float*)d_in[13];
    const float* fc2_b   = (const float*)d_in[14];
    float* out = (float*)d_out;

    cudaFuncSetAttribute(gemm_bf<128, 0>, cudaFuncAttributeMaxDynamicSharedMemorySize, SMTOT);
    cudaFuncSetAttribute(gemm_bf<128, 1>, cudaFuncAttributeMaxDynamicSharedMemorySize, SMTOT);
    cudaFuncSetAttribute(gemm_bf<128, 2>, cudaFuncAttributeMaxDynamicSharedMemorySize, SMTOT);
    cudaFuncSetAttribute(gemm_bf<512, 3>, cudaFuncAttributeMaxDynamicSharedMemorySize, SMTOT);

    __nv_bfloat16 *p_qkvw, *p_projw, *p_fc1w, *p_fc2w;
    __nv_bfloat16 *p_xw, *p_obuf, *p_y, *p_h1;
    cudaGetSymbolAddress((void**)&p_qkvw, g_qkvw);
    cudaGetSymbolAddress((void**)&p_projw, g_projw);
    cudaGetSymbolAddress((void**)&p_fc1w, g_fc1w);
    cudaGetSymbolAddress((void**)&p_fc2w, g_fc2w);
    cudaGetSymbolAddress((void**)&p_xw, g_xw_bf);
    cudaGetSymbolAddress((void**)&p_obuf, g_obuf_bf);
    cudaGetSymbolAddress((void**)&p_y, g_y_bf);
    cudaGetSymbolAddress((void**)&p_h1, g_h1_bf);

    // weight conversion (tiny)
    cvt_kernel<<<48, 256>>>(qkv_w, p_qkvw, 3*CC*CC);
    cvt_kernel<<<16, 256>>>(proj_w, p_projw, CC*CC);
    cvt_kernel<<<64, 256>>>(fc1_w, p_fc1w, HID*CC);
    cvt_kernel<<<64, 256>>>(fc2_w, p_fc2w, CC*HID);

    ln1_gather_kernel<<<MROWS / 8, 256>>>(x, norm1_w, norm1_b);
    gemm_bf<128, 0><<<dim3(MROWS / 128, 3), 256, SMTOT>>>(p_xw, p_qkvw, qkv_b, nullptr, nullptr);
    attn_kernel<<<dim3(BB * NW, NH4), 128>>>(rpb);
    gemm_bf<128, 1><<<dim3(MROWS / 128, 1), 256, SMTOT>>>(p_obuf, p_projw, proj_b, x, nullptr);
    ln2_kernel<<<MROWS / 8, 256>>>(norm2_w, norm2_b);
    gemm_bf<128, 2><<<dim3(MROWS / 128, 4), 256, SMTOT>>>(p_y, p_fc1w, fc1_b, nullptr, nullptr);
    gemm_bf<512, 3><<<dim3(MROWS / 128, 1), 256, SMTOT>>>(p_h1, p_fc2w, fc2_b, nullptr, out);
}

// round 6
// speedup vs baseline: 5.6127x; 1.0057x over previous
#include <cuda_runtime.h>
#include <cuda_bf16.h>
#include <math.h>
#include <cstdint>

// ---------------- problem constants ----------------
#define HH     112
#define WW     112
#define CC     128
#define SHIFT3 3
#define NH4    4
#define BB     8
#define HID    512
#define NN     49
#define HD32   32
#define NW     256
#define LTOK   (HH*WW)      // 12544
#define MROWS  (BB*NW*NN)   // 100352 = 784*128
#define SCALEF 0.17677669529663687f

// ---------------- scratch ----------------
__device__ __nv_bfloat16 g_xw_bf  [MROWS*CC];
__device__ __nv_bfloat16 g_obuf_bf[MROWS*CC];
__device__ __nv_bfloat16 g_y_bf   [MROWS*CC];
__device__ __nv_bfloat16 g_h1_bf  [MROWS*HID];
__device__ __nv_bfloat16 g_q_bf   [MROWS*CC];
__device__ __nv_bfloat16 g_k_bf   [MROWS*CC];
__device__ __nv_bfloat16 g_v_bf   [MROWS*CC];
__device__ float g_xres[MROWS*CC];
__device__ __nv_bfloat16 g_qkvw[3*CC*CC];
__device__ __nv_bfloat16 g_projw[CC*CC];
__device__ __nv_bfloat16 g_fc1w[HID*CC];
__device__ __nv_bfloat16 g_fc2w[CC*HID];

// ---------------- helpers ----------------
__device__ __forceinline__ uint32_t smem_u32(const void* p) {
    uint32_t a;
    asm("{ .reg .u64 t; cvta.to.shared.u64 t, %1; cvt.u32.u64 %0, t; }" : "=r"(a) : "l"(p));
    return a;
}
__device__ __forceinline__ uint32_t pack_bf2(float lo, float hi) {
    __nv_bfloat162 v = __floats2bfloat162_rn(lo, hi);
    return *(uint32_t*)&v;
}
__device__ __forceinline__ void mma_bf16(float& c0, float& c1, float& c2, float& c3,
                                         uint32_t a0, uint32_t a1, uint32_t a2, uint32_t a3,
                                         uint32_t b0, uint32_t b1) {
    asm volatile("mma.sync.aligned.m16n8k16.row.col.f32.bf16.bf16.f32 "
                 "{%0,%1,%2,%3}, {%4,%5,%6,%7}, {%8,%9}, {%0,%1,%2,%3};"
                 : "+f"(c0), "+f"(c1), "+f"(c2), "+f"(c3)
                 : "r"(a0), "r"(a1), "r"(a2), "r"(a3), "r"(b0), "r"(b1));
}
#define LDSM4(r0, r1, r2, r3, addr) \
    asm volatile("ldmatrix.sync.aligned.m8n8.x4.shared.b16 {%0,%1,%2,%3}, [%4];" \
                 : "=r"(r0), "=r"(r1), "=r"(r2), "=r"(r3) : "r"(addr))
#define CP_ASYNC16(dst, src) \
    asm volatile("cp.async.cg.shared.global [%0], [%1], 16;" :: "r"(dst), "l"(src))
#define CP_COMMIT() asm volatile("cp.async.commit_group;" ::: "memory")
#define CP_WAIT0()  asm volatile("cp.async.wait_group 0;" ::: "memory")
#define CP_WAIT1()  asm volatile("cp.async.wait_group 1;" ::: "memory")

// ---------------- merged fp32 -> bf16 weight conversion ----------------
__global__ void cvt_all(const float* __restrict__ qkv, const float* __restrict__ proj,
                        const float* __restrict__ fc1, const float* __restrict__ fc2) {
    int i = (blockIdx.x * 256 + threadIdx.x) * 4;
    const float* src;
    __nv_bfloat16* dst;
    int off;
    if (i < 49152)       { src = qkv;  dst = g_qkvw;  off = i; }
    else if (i < 65536)  { src = proj; dst = g_projw; off = i - 49152; }
    else if (i < 131072) { src = fc1;  dst = g_fc1w;  off = i - 65536; }
    else                 { src = fc2;  dst = g_fc2w;  off = i - 131072; }
    float4 v = *(const float4*)(src + off);
    uint2 pk;
    pk.x = pack_bf2(v.x, v.y);
    pk.y = pack_bf2(v.z, v.w);
    *(uint2*)(dst + off) = pk;
}

// ---------------- LN1 + roll(-3,-3) + window partition -> bf16 ----------------
__global__ void ln1_gather_kernel(const float* __restrict__ x,
                                  const float* __restrict__ w,
                                  const float* __restrict__ b) {
    int row  = blockIdx.x * 8 + (threadIdx.x >> 5);
    int lane = threadIdx.x & 31;
    int bn = row / NN, n = row - bn * NN;
    int bi = bn >> 8, win = bn & 255;
    int wi = win >> 4, wj = win & 15;
    int r = n / 7, c = n - r * 7;
    int si = wi * 7 + r + SHIFT3; if (si >= HH) si -= HH;
    int sj = wj * 7 + c + SHIFT3; if (sj >= WW) sj -= WW;
    const float4* src = (const float4*)(x + ((size_t)bi * LTOK + si * WW + sj) * CC);
    float4 v = src[lane];
    float s = v.x + v.y + v.z + v.w;
    #pragma unroll
    for (int o = 16; o; o >>= 1) s += __shfl_xor_sync(0xffffffffu, s, o);
    float mean = s * (1.0f / 128.0f);
    float dx = v.x - mean, dy = v.y - mean, dz = v.z - mean, dw = v.w - mean;
    float q = dx*dx + dy*dy + dz*dz + dw*dw;
    #pragma unroll
    for (int o = 16; o; o >>= 1) q += __shfl_xor_sync(0xffffffffu, q, o);
    float inv = rsqrtf(q * (1.0f / 128.0f) + 1e-5f);
    float4 wv = ((const float4*)w)[lane];
    float4 bv = ((const float4*)b)[lane];
    uint2 pk;
    pk.x = pack_bf2(dx * inv * wv.x + bv.x, dy * inv * wv.y + bv.y);
    pk.y = pack_bf2(dz * inv * wv.z + bv.z, dw * inv * wv.w + bv.w);
    *(uint2*)(g_xw_bf + (size_t)row * CC + lane * 4) = pk;
}

// ---------------- LN2 -> bf16 ----------------
__global__ void ln2_kernel(const float* __restrict__ w, const float* __restrict__ b) {
    int row  = blockIdx.x * 8 + (threadIdx.x >> 5);
    int lane = threadIdx.x & 31;
    float4 v = ((const float4*)(g_xres + (size_t)row * CC))[lane];
    float s = v.x + v.y + v.z + v.w;
    #pragma unroll
    for (int o = 16; o; o >>= 1) s += __shfl_xor_sync(0xffffffffu, s, o);
    float mean = s * (1.0f / 128.0f);
    float dx = v.x - mean, dy = v.y - mean, dz = v.z - mean, dw = v.w - mean;
    float q = dx*dx + dy*dy + dz*dz + dw*dw;
    #pragma unroll
    for (int o = 16; o; o >>= 1) q += __shfl_xor_sync(0xffffffffu, q, o);
    float inv = rsqrtf(q * (1.0f / 128.0f) + 1e-5f);
    float4 wv = ((const float4*)w)[lane];
    float4 bv = ((const float4*)b)[lane];
    uint2 pk;
    pk.x = pack_bf2(dx * inv * wv.x + bv.x, dy * inv * wv.y + bv.y);
    pk.y = pack_bf2(dz * inv * wv.z + bv.z, dw * inv * wv.w + bv.w);
    *(uint2*)(g_y_bf + (size_t)row * CC + lane * 4) = pk;
}

// =====================================================================
// Shared GEMM machinery: CTA tile 128x128 output, 8 warps (4m x 2n),
// warp tile 32x64 = 2x8 m16n8k16 frags, ldmatrix fragment loads.
// smem rows: 144B stride (64 k bf16 + 16B pad) -> conflict-free ldmatrix.
// =====================================================================
#define SMTOT 73728

// epilogue dispatcher (thread owns rows wm+mi*16+g(+8), cols wn+ni*8+2t(+1))
template<int MODE>
__device__ __forceinline__ void gemm_epilogue(
    float acc[2][8][4], int yb, int m0, int wm, int wn, int g, int t,
    const float* __restrict__ bias, const float* __restrict__ xin,
    float* __restrict__ outp) {
    #pragma unroll
    for (int mi = 0; mi < 2; ++mi) {
        #pragma unroll
        for (int half = 0; half < 2; ++half) {
            int m = m0 + wm + mi * 16 + g + half * 8;
            if (MODE == 0) {
                int bn = m / NN, n = m - bn * NN;
                __nv_bfloat16* dst = (yb == 0) ? g_q_bf : (yb == 1) ? g_k_bf : g_v_bf;
                float scl = (yb == 0) ? SCALEF : 1.0f;
                #pragma unroll
                for (int ni = 0; ni < 8; ++ni) {
                    int ol = wn + ni * 8 + 2 * t;
                    int hh = ol >> 5, dd = ol & 31;
                    float vx = (acc[mi][ni][half*2+0] + bias[yb * 128 + ol])     * scl;
                    float vy = (acc[mi][ni][half*2+1] + bias[yb * 128 + ol + 1]) * scl;
                    *(uint32_t*)(dst + (size_t)(bn * NH4 + hh) * (NN * HD32) + n * HD32 + dd) =
                        pack_bf2(vx, vy);
                }
            } else if (MODE == 1) {
                int bn = m / NN, n = m - bn * NN;
                int bi = bn >> 8, win = bn & 255;
                int wi = win >> 4, wj = win & 15;
                int r = n / 7, cq = n - r * 7;
                int ii = wi * 7 + r + SHIFT3;  if (ii >= HH) ii -= HH;
                int jj = wj * 7 + cq + SHIFT3; if (jj >= WW) jj -= WW;
                size_t tok = (size_t)bi * LTOK + ii * WW + jj;
                #pragma unroll
                for (int ni = 0; ni < 8; ++ni) {
                    int ol = wn + ni * 8 + 2 * t;
                    float2 xr = *(const float2*)(xin + tok * CC + ol);
                    float2 v;
                    v.x = acc[mi][ni][half*2+0] + bias[ol]     + xr.x;
                    v.y = acc[mi][ni][half*2+1] + bias[ol + 1] + xr.y;
                    *(float2*)(g_xres + tok * CC + ol) = v;
                }
            } else if (MODE == 2) {
                #pragma unroll
                for (int ni = 0; ni < 8; ++ni) {
                    int ol = wn + ni * 8 + 2 * t;
                    float a = acc[mi][ni][half*2+0] + bias[yb * 128 + ol];
                    float b = acc[mi][ni][half*2+1] + bias[yb * 128 + ol + 1];
                    float ga = 0.5f * a * (1.0f + erff(a * 0.70710678118654752f));
                    float gb = 0.5f * b * (1.0f + erff(b * 0.70710678118654752f));
                    *(uint32_t*)(g_h1_bf + (size_t)m * HID + yb * 128 + ol) = pack_bf2(ga, gb);
                }
            } else {
                #pragma unroll
                for (int ni = 0; ni < 8; ++ni) {
                    int ol = wn + ni * 8 + 2 * t;
                    float2 xr = *(const float2*)(g_xres + (size_t)m * CC + ol);
                    float2 v;
                    v.x = acc[mi][ni][half*2+0] + bias[ol]     + xr.x;
                    v.y = acc[mi][ni][half*2+1] + bias[ol + 1] + xr.y;
                    *(float2*)(outp + (size_t)m * CC + ol) = v;
                }
            }
        }
    }
}

// one k64-chunk of mma work (4 x k16 steps), ldmatrix loads
__device__ __forceinline__ void gemm_chunk_mma(
    float acc[2][8][4], uint32_t Ab, uint32_t Bb,
    int wm, int wn, uint32_t a_lane_off, uint32_t b_lane_off) {
    #pragma unroll
    for (int kk2 = 0; kk2 < 32; kk2 += 8) {
        uint32_t af[2][4];
        #pragma unroll
        for (int mi = 0; mi < 2; ++mi)
            LDSM4(af[mi][0], af[mi][1], af[mi][2], af[mi][3],
                  Ab + (wm + mi * 16) * 144 + kk2 * 4 + a_lane_off);
        uint32_t bf[8][2];
        #pragma unroll
        for (int p = 0; p < 4; ++p)
            LDSM4(bf[2*p][0], bf[2*p][1], bf[2*p+1][0], bf[2*p+1][1],
                  Bb + (wn + p * 16) * 144 + kk2 * 4 + b_lane_off);
        #pragma unroll
        for (int mi = 0; mi < 2; ++mi)
            #pragma unroll
            for (int ni = 0; ni < 8; ++ni)
                mma_bf16(acc[mi][ni][0], acc[mi][ni][1], acc[mi][ni][2], acc[mi][ni][3],
                         af[mi][0], af[mi][1], af[mi][2], af[mi][3],
                         bf[ni][0], bf[ni][1]);
    }
}

// ---------------- K=128 GEMM, A tile resident, NB weight blocks streamed ----------
// smem: A chunk c at c*18432 (held whole kernel); B double buffer at 36864 + buf*18432
template<int NB, int MODE>
__global__ void __launch_bounds__(256, 2)
gemm_multi(const __nv_bfloat16* __restrict__ A, const __nv_bfloat16* __restrict__ Wb,
           const float* __restrict__ bias, const float* __restrict__ xin,
           float* __restrict__ outp) {
    extern __shared__ char smem[];
    const uint32_t sbase = smem_u32(smem);
    const int m0 = blockIdx.x * 128;
    const int tid  = threadIdx.x;
    const int wid  = tid >> 5;
    const int lane = tid & 31;
    const int g = lane >> 2;
    const int t = lane & 3;
    const int wm = (wid >> 1) * 32;
    const int wn = (wid & 1) * 64;
    const uint32_t a_lane_off = ((lane & 7) + ((lane >> 3) & 1) * 8) * 144 + (lane >> 4) * 16;
    const uint32_t b_lane_off = (((lane >> 4) & 1) * 8 + (lane & 7)) * 144 + ((lane >> 3) & 1) * 16;

    // stage full A (both 64-k chunks)
    #pragma unroll
    for (int it = 0; it < 8; ++it) {
        int idx = tid + it * 256;
        int r = idx >> 4, cc = idx & 15;
        uint32_t da = sbase + (cc >> 3) * 18432 + r * 144 + (cc & 7) * 16;
        CP_ASYNC16(da, A + (size_t)(m0 + r) * 128 + cc * 8);
    }
    // stage B(yb=0, c=0) into buf 0
    #pragma unroll
    for (int it = 0; it < 4; ++it) {
        int idx = tid + it * 256;
        int r = idx >> 3, cc2 = idx & 7;
        CP_ASYNC16(sbase + 36864 + r * 144 + cc2 * 16, Wb + (size_t)r * 128 + cc2 * 8);
    }
    CP_COMMIT();

    float acc[2][8][4];
    #pragma unroll 1
    for (int s = 0; s < 2 * NB; ++s) {
        int c = s & 1, buf = s & 1, yb = s >> 1;
        if (c == 0) {
            #pragma unroll
            for (int mi = 0; mi < 2; ++mi)
                #pragma unroll
                for (int ni = 0; ni < 8; ++ni)
                    #pragma unroll
                    for (int q = 0; q < 4; ++q) acc[mi][ni][q] = 0.0f;
        }
        if (s + 1 < 2 * NB) {
            int yb2 = (s + 1) >> 1, c2 = (s + 1) & 1, buf2 = (s + 1) & 1;
            #pragma unroll
            for (int it = 0; it < 4; ++it) {
                int idx = tid + it * 256;
                int r = idx >> 3, cc2 = idx & 7;
                CP_ASYNC16(sbase + 36864 + buf2 * 18432 + r * 144 + cc2 * 16,
                           Wb + (size_t)(yb2 * 128 + r) * 128 + c2 * 64 + cc2 * 8);
            }
            CP_COMMIT();
            CP_WAIT1();
        } else {
            CP_WAIT0();
        }
        __syncthreads();
        gemm_chunk_mma(acc, sbase + c * 18432, sbase + 36864 + buf * 18432,
                       wm, wn, a_lane_off, b_lane_off);
        __syncthreads();
        if (c == 1)
            gemm_epilogue<MODE>(acc, yb, m0, wm, wn, g, t, bias, xin, outp);
    }
}

// ---------------- K=512 streaming GEMM (fc2) ----------------
// smem: double buffer; buffer sel at sel*36864: A at +0, B at +18432
template<int KDIM, int MODE>
__global__ void __launch_bounds__(256, 2)
gemm_stream(const __nv_bfloat16* __restrict__ A, const __nv_bfloat16* __restrict__ Wb,
            const float* __restrict__ bias, const float* __restrict__ xin,
            float* __restrict__ outp) {
    extern __shared__ char smem[];
    const uint32_t sbase = smem_u32(smem);
    const int m0 = blockIdx.x * 128;
    const int tid  = threadIdx.x;
    const int wid  = tid >> 5;
    const int lane = tid & 31;
    const int g = lane >> 2;
    const int t = lane & 3;
    const int wm = (wid >> 1) * 32;
    const int wn = (wid & 1) * 64;
    const uint32_t a_lane_off = ((lane & 7) + ((lane >> 3) & 1) * 8) * 144 + (lane >> 4) * 16;
    const uint32_t b_lane_off = (((lane >> 4) & 1) * 8 + (lane & 7)) * 144 + ((lane >> 3) & 1) * 16;
    const int NC = KDIM / 64;

    float acc[2][8][4];
    #pragma unroll
    for (int mi = 0; mi < 2; ++mi)
        #pragma unroll
        for (int ni = 0; ni < 8; ++ni)
            #pragma unroll
            for (int q = 0; q < 4; ++q) acc[mi][ni][q] = 0.0f;

    #pragma unroll
    for (int it = 0; it < 4; ++it) {
        int idx = tid + it * 256;
        int r = idx >> 3, cc = idx & 7;
        uint32_t da = sbase + r * 144 + cc * 16;
        CP_ASYNC16(da, A + (size_t)(m0 + r) * KDIM + cc * 8);
        CP_ASYNC16(da + 18432, Wb + (size_t)r * KDIM + cc * 8);
    }
    CP_COMMIT();

    #pragma unroll 1
    for (int c = 0; c < NC; ++c) {
        if (c + 1 < NC) {
            int k0 = (c + 1) * 64;
            int sel = (c + 1) & 1;
            #pragma unroll
            for (int it = 0; it < 4; ++it) {
                int idx = tid + it * 256;
                int r = idx >> 3, cc = idx & 7;
                uint32_t da = sbase + sel * 36864 + r * 144 + cc * 16;
                CP_ASYNC16(da, A + (size_t)(m0 + r) * KDIM + k0 + cc * 8);
                CP_ASYNC16(da + 18432, Wb + (size_t)r * KDIM + k0 + cc * 8);
            }
            CP_COMMIT();
            CP_WAIT1();
        } else {
            CP_WAIT0();
        }
        __syncthreads();
        uint32_t base = sbase + (c & 1) * 36864;
        gemm_chunk_mma(acc, base, base + 18432, wm, wn, a_lane_off, b_lane_off);
        __syncthreads();
    }
    gemm_epilogue<MODE>(acc, 0, m0, wm, wn, g, t, bias, xin, outp);
}

// ---------------- windowed attention (bf16 inputs, register-tiled) ----------------
__device__ __forceinline__ int regionf(int i) { return (i < 105) ? 0 : ((i < 109) ? 1 : 2); }

__global__ void __launch_bounds__(128)
attn_kernel(const float* __restrict__ rpb) {
    int bn = blockIdx.x;
    int h  = blockIdx.y;
    __shared__ float qs[NN * HD32];
    __shared__ float ks[NN * HD32];
    __shared__ float vs[NN * HD32];
    __shared__ float sc[NN * 52];
    __shared__ float bs[169];
    int tid = threadIdx.x;

    size_t base = ((size_t)(bn * NH4 + h)) * NN * HD32;
    const uint4* qsrc = (const uint4*)(g_q_bf + base);
    const uint4* ksrc = (const uint4*)(g_k_bf + base);
    const uint4* vsrc = (const uint4*)(g_v_bf + base);
    for (int idx = tid; idx < 196; idx += 128) {
        uint4 u;
        float* d;
        u = qsrc[idx]; d = qs + idx * 8;
        {
            float2 f0 = __bfloat1622float2(*(__nv_bfloat162*)&u.x);
            float2 f1 = __bfloat1622float2(*(__nv_bfloat162*)&u.y);
            float2 f2 = __bfloat1622float2(*(__nv_bfloat162*)&u.z);
            float2 f3 = __bfloat1622float2(*(__nv_bfloat162*)&u.w);
            d[0]=f0.x; d[1]=f0.y; d[2]=f1.x; d[3]=f1.y;
            d[4]=f2.x; d[5]=f2.y; d[6]=f3.x; d[7]=f3.y;
        }
        u = ksrc[idx]; d = ks + idx * 8;
        {
            float2 f0 = __bfloat1622float2(*(__nv_bfloat162*)&u.x);
            float2 f1 = __bfloat1622float2(*(__nv_bfloat162*)&u.y);
            float2 f2 = __bfloat1622float2(*(__nv_bfloat162*)&u.z);
            float2 f3 = __bfloat1622float2(*(__nv_bfloat162*)&u.w);
            d[0]=f0.x; d[1]=f0.y; d[2]=f1.x; d[3]=f1.y;
            d[4]=f2.x; d[5]=f2.y; d[6]=f3.x; d[7]=f3.y;
        }
        u = vsrc[idx]; d = vs + idx * 8;
        {
            float2 f0 = __bfloat1622float2(*(__nv_bfloat162*)&u.x);
            float2 f1 = __bfloat1622float2(*(__nv_bfloat162*)&u.y);
            float2 f2 = __bfloat1622float2(*(__nv_bfloat162*)&u.z);
            float2 f3 = __bfloat1622float2(*(__nv_bfloat162*)&u.w);
            d[0]=f0.x; d[1]=f0.y; d[2]=f1.x; d[3]=f1.y;
            d[4]=f2.x; d[5]=f2.y; d[6]=f3.x; d[7]=f3.y;
        }
    }
    for (int i = tid; i < 169; i += 128) bs[i] = rpb[i * NH4 + h];
    __syncthreads();

    int win = bn & 255, wi = win >> 4, wj = win & 15;

    // QK^T + bias + mask, 4x4 register tiles (13x13 = 169 tiles)
    for (int tl = tid; tl < 169; tl += 128) {
        int tn = tl / 13, tm = tl - tn * 13;
        int n0 = tn * 4, m0 = tm * 4;
        float acc[4][4];
        #pragma unroll
        for (int i = 0; i < 4; ++i)
            #pragma unroll
            for (int j = 0; j < 4; ++j) acc[i][j] = 0.0f;
        #pragma unroll
        for (int kc = 0; kc < 32; kc += 8) {
            float4 qa[4][2], ka[4][2];
            #pragma unroll
            for (int i = 0; i < 4; ++i) {
                qa[i][0] = *(const float4*)(qs + (n0 + i) * HD32 + kc);
                qa[i][1] = *(const float4*)(qs + (n0 + i) * HD32 + kc + 4);
                ka[i][0] = *(const float4*)(ks + (m0 + i) * HD32 + kc);
                ka[i][1] = *(const float4*)(ks + (m0 + i) * HD32 + kc + 4);
            }
            #pragma unroll
            for (int i = 0; i < 4; ++i)
                #pragma unroll
                for (int j = 0; j < 4; ++j) {
                    acc[i][j] += qa[i][0].x * ka[j][0].x + qa[i][0].y * ka[j][0].y
                               + qa[i][0].z * ka[j][0].z + qa[i][0].w * ka[j][0].w
                               + qa[i][1].x * ka[j][1].x + qa[i][1].y * ka[j][1].y
                               + qa[i][1].z * ka[j][1].z + qa[i][1].w * ka[j][1].w;
                }
        }
        #pragma unroll
        for (int i = 0; i < 4; ++i) {
            int n = n0 + i;
            if (n >= NN) break;
            int r1 = n / 7, c1 = n - r1 * 7;
            int reg1 = regionf(wi * 7 + r1) * 3 + regionf(wj * 7 + c1);
            #pragma unroll
            for (int j = 0; j < 4; ++j) {
                int m = m0 + j;
                if (m >= NN) continue;
                int r2 = m / 7, c2 = m - r2 * 7;
                float v = acc[i][j] + bs[(r1 - r2 + 6) * 13 + (c1 - c2 + 6)];
                int reg2 = regionf(wi * 7 + r2) * 3 + regionf(wj * 7 + c2);
                if (reg1 != reg2) v -= 100.0f;
                sc[n * 52 + m] = v;
            }
        }
    }
    __syncthreads();

    // softmax (thread per row)
    if (tid < NN) {
        float* row = sc + tid * 52;
        float mx = -1e30f;
        #pragma unroll 7
        for (int m2 = 0; m2 < NN; ++m2) mx = fmaxf(mx, row[m2]);
        float s = 0.0f;
        #pragma unroll 7
        for (int m2 = 0; m2 < NN; ++m2) { float e = __expf(row[m2] - mx); row[m2] = e; s += e; }
        float inv = 1.0f / s;
        #pragma unroll 7
        for (int m2 = 0; m2 < NN; ++m2) row[m2] *= inv;
    }
    __syncthreads();

    // P @ V, 2n x 8d tiling; bf16 output
    if (tid < 100) {
        int n0 = (tid >> 2) * 2;
        int d0 = (tid & 3) * 8;
        float a0[8], a1[8];
        #pragma unroll
        for (int i = 0; i < 8; ++i) { a0[i] = 0.0f; a1[i] = 0.0f; }
        const float* p0 = sc + n0 * 52;
        const float* p1 = sc + (n0 + 1) * 52;
        #pragma unroll 7
        for (int m2 = 0; m2 < NN; ++m2) {
            float w0 = p0[m2], w1 = p1[m2];
            float4 va = *(const float4*)(vs + m2 * HD32 + d0);
            float4 vb = *(const float4*)(vs + m2 * HD32 + d0 + 4);
            a0[0] += w0 * va.x; a0[1] += w0 * va.y; a0[2] += w0 * va.z; a0[3] += w0 * va.w;
            a0[4] += w0 * vb.x; a0[5] += w0 * vb.y; a0[6] += w0 * vb.z; a0[7] += w0 * vb.w;
            a1[0] += w1 * va.x; a1[1] += w1 * va.y; a1[2] += w1 * va.z; a1[3] += w1 * va.w;
            a1[4] += w1 * vb.x; a1[5] += w1 * vb.y; a1[6] += w1 * vb.z; a1[7] += w1 * vb.w;
        }
        __nv_bfloat16* o = g_obuf_bf + ((size_t)(bn * NN + n0)) * CC + h * HD32 + d0;
        uint4 pk;
        pk.x = pack_bf2(a0[0], a0[1]);
        pk.y = pack_bf2(a0[2], a0[3]);
        pk.z = pack_bf2(a0[4], a0[5]);
        pk.w = pack_bf2(a0[6], a0[7]);
        *(uint4*)o = pk;
        if (n0 + 1 < NN) {
            pk.x = pack_bf2(a1[0], a1[1]);
            pk.y = pack_bf2(a1[2], a1[3]);
            pk.z = pack_bf2(a1[4], a1[5]);
            pk.w = pack_bf2(a1[6], a1[7]);
            *(uint4*)(o + CC) = pk;
        }
    }
}

// ---------------- launch ----------------
extern "C" void kernel_launch(void* const* d_in, const int* in_sizes, int n_in,
                              void* d_out, int out_size) {
    const float* x       = (const float*)d_in[0];
    const float* norm1_w = (const float*)d_in[2];
    const float* norm1_b = (const float*)d_in[3];
    const float* qkv_w   = (const float*)d_in[4];
    const float* qkv_b   = (const float*)d_in[5];
    const float* rpb     = (const float*)d_in[6];
    const float* proj_w  = (const float*)d_in[7];
    const float* proj_b  = (const float*)d_in[8];
    const float* norm2_w = (const float*)d_in[9];
    const float* norm2_b = (const float*)d_in[10];
    const float* fc1_w   = (const float*)d_in[11];
    const float* fc1_b   = (const float*)d_in[12];
    const float* fc2_w   = (const float*)d_in[13];
    const float* fc2_b   = (const float*)d_in[14];
    float* out = (float*)d_out;

    cudaFuncSetAttribute(gemm_multi<3, 0>, cudaFuncAttributeMaxDynamicSharedMemorySize, SMTOT);
    cudaFuncSetAttribute(gemm_multi<1, 1>, cudaFuncAttributeMaxDynamicSharedMemorySize, SMTOT);
    cudaFuncSetAttribute(gemm_multi<4, 2>, cudaFuncAttributeMaxDynamicSharedMemorySize, SMTOT);
    cudaFuncSetAttribute(gemm_stream<512, 3>, cudaFuncAttributeMaxDynamicSharedMemorySize, SMTOT);

    __nv_bfloat16 *p_qkvw, *p_projw, *p_fc1w, *p_fc2w;
    __nv_bfloat16 *p_xw, *p_obuf, *p_y, *p_h1;
    cudaGetSymbolAddress((void**)&p_qkvw, g_qkvw);
    cudaGetSymbolAddress((void**)&p_projw, g_projw);
    cudaGetSymbolAddress((void**)&p_fc1w, g_fc1w);
    cudaGetSymbolAddress((void**)&p_fc2w, g_fc2w);
    cudaGetSymbolAddress((void**)&p_xw, g_xw_bf);
    cudaGetSymbolAddress((void**)&p_obuf, g_obuf_bf);
    cudaGetSymbolAddress((void**)&p_y, g_y_bf);
    cudaGetSymbolAddress((void**)&p_h1, g_h1_bf);

    cvt_all<<<192, 256>>>(qkv_w, proj_w, fc1_w, fc2_w);
    ln1_gather_kernel<<<MROWS / 8, 256>>>(x, norm1_w, norm1_b);
    gemm_multi<3, 0><<<MROWS / 128, 256, SMTOT>>>(p_xw, p_qkvw, qkv_b, nullptr, nullptr);
    attn_kernel<<<dim3(BB * NW, NH4), 128>>>(rpb);
    gemm_multi<1, 1><<<MROWS / 128, 256, SMTOT>>>(p_obuf, p_projw, proj_b, x, nullptr);
    ln2_kernel<<<MROWS / 8, 256>>>(norm2_w, norm2_b);
    gemm_multi<4, 2><<<MROWS / 128, 256, SMTOT>>>(p_y, p_fc1w, fc1_b, nullptr, nullptr);
    gemm_stream<512, 3><<<MROWS / 128, 256, SMTOT>>>(p_h1, p_fc2w, fc2_b, nullptr, out);
}

// round 7
// speedup vs baseline: 9.6168x; 1.7134x over previous
#include <cuda_runtime.h>
#include <cuda_bf16.h>
#include <math.h>
#include <cstdint>

// ---------------- problem constants ----------------
#define HH     112
#define WW     112
#define CC     128
#define SHIFT3 3
#define NH4    4
#define BB     8
#define HID    512
#define NN     49
#define HD32   32
#define NW     256
#define LTOK   (HH*WW)      // 12544
#define MROWS  (BB*NW*NN)   // 100352 = 784*128
#define SCALEF 0.17677669529663687f

// ---------------- scratch ----------------
__device__ __nv_bfloat16 g_xw_bf  [MROWS*CC];
__device__ __nv_bfloat16 g_obuf_bf[MROWS*CC];
__device__ __nv_bfloat16 g_y_bf   [MROWS*CC];
__device__ __nv_bfloat16 g_h1_bf  [MROWS*HID];
__device__ __nv_bfloat16 g_q_bf   [MROWS*CC];
__device__ __nv_bfloat16 g_k_bf   [MROWS*CC];
__device__ __nv_bfloat16 g_v_bf   [MROWS*CC];
__device__ float g_xres[MROWS*CC];
__device__ __nv_bfloat16 g_qkvw[3*CC*CC];
__device__ __nv_bfloat16 g_projw[CC*CC];
__device__ __nv_bfloat16 g_fc1w[HID*CC];
__device__ __nv_bfloat16 g_fc2w[CC*HID];

// ---------------- helpers ----------------
__device__ __forceinline__ uint32_t smem_u32(const void* p) {
    uint32_t a;
    asm("{ .reg .u64 t; cvta.to.shared.u64 t, %1; cvt.u32.u64 %0, t; }" : "=r"(a) : "l"(p));
    return a;
}
__device__ __forceinline__ uint32_t pack_bf2(float lo, float hi) {
    __nv_bfloat162 v = __floats2bfloat162_rn(lo, hi);
    return *(uint32_t*)&v;
}
__device__ __forceinline__ void mma_bf16(float& c0, float& c1, float& c2, float& c3,
                                         uint32_t a0, uint32_t a1, uint32_t a2, uint32_t a3,
                                         uint32_t b0, uint32_t b1) {
    asm volatile("mma.sync.aligned.m16n8k16.row.col.f32.bf16.bf16.f32 "
                 "{%0,%1,%2,%3}, {%4,%5,%6,%7}, {%8,%9}, {%0,%1,%2,%3};"
                 : "+f"(c0), "+f"(c1), "+f"(c2), "+f"(c3)
                 : "r"(a0), "r"(a1), "r"(a2), "r"(a3), "r"(b0), "r"(b1));
}
#define LDSM4(r0, r1, r2, r3, addr) \
    asm volatile("ldmatrix.sync.aligned.m8n8.x4.shared.b16 {%0,%1,%2,%3}, [%4];" \
                 : "=r"(r0), "=r"(r1), "=r"(r2), "=r"(r3) : "r"(addr))
#define LDSM4T(r0, r1, r2, r3, addr) \
    asm volatile("ldmatrix.sync.aligned.m8n8.x4.trans.shared.b16 {%0,%1,%2,%3}, [%4];" \
                 : "=r"(r0), "=r"(r1), "=r"(r2), "=r"(r3) : "r"(addr))
#define CP_ASYNC16(dst, src) \
    asm volatile("cp.async.cg.shared.global [%0], [%1], 16;" :: "r"(dst), "l"(src))
#define CP_COMMIT() asm volatile("cp.async.commit_group;" ::: "memory")
#define CP_WAIT0()  asm volatile("cp.async.wait_group 0;" ::: "memory")
#define CP_WAIT1()  asm volatile("cp.async.wait_group 1;" ::: "memory")

// ---------------- merged fp32 -> bf16 weight conversion ----------------
__global__ void cvt_all(const float* __restrict__ qkv, const float* __restrict__ proj,
                        const float* __restrict__ fc1, const float* __restrict__ fc2) {
    int i = (blockIdx.x * 256 + threadIdx.x) * 4;
    const float* src;
    __nv_bfloat16* dst;
    int off;
    if (i < 49152)       { src = qkv;  dst = g_qkvw;  off = i; }
    else if (i < 65536)  { src = proj; dst = g_projw; off = i - 49152; }
    else if (i < 131072) { src = fc1;  dst = g_fc1w;  off = i - 65536; }
    else                 { src = fc2;  dst = g_fc2w;  off = i - 131072; }
    float4 v = *(const float4*)(src + off);
    uint2 pk;
    pk.x = pack_bf2(v.x, v.y);
    pk.y = pack_bf2(v.z, v.w);
    *(uint2*)(dst + off) = pk;
}

// ---------------- LN1 + roll(-3,-3) + window partition -> bf16 ----------------
__global__ void ln1_gather_kernel(const float* __restrict__ x,
                                  const float* __restrict__ w,
                                  const float* __restrict__ b) {
    int row  = blockIdx.x * 8 + (threadIdx.x >> 5);
    int lane = threadIdx.x & 31;
    int bn = row / NN, n = row - bn * NN;
    int bi = bn >> 8, win = bn & 255;
    int wi = win >> 4, wj = win & 15;
    int r = n / 7, c = n - r * 7;
    int si = wi * 7 + r + SHIFT3; if (si >= HH) si -= HH;
    int sj = wj * 7 + c + SHIFT3; if (sj >= WW) sj -= WW;
    const float4* src = (const float4*)(x + ((size_t)bi * LTOK + si * WW + sj) * CC);
    float4 v = src[lane];
    float s = v.x + v.y + v.z + v.w;
    #pragma unroll
    for (int o = 16; o; o >>= 1) s += __shfl_xor_sync(0xffffffffu, s, o);
    float mean = s * (1.0f / 128.0f);
    float dx = v.x - mean, dy = v.y - mean, dz = v.z - mean, dw = v.w - mean;
    float q = dx*dx + dy*dy + dz*dz + dw*dw;
    #pragma unroll
    for (int o = 16; o; o >>= 1) q += __shfl_xor_sync(0xffffffffu, q, o);
    float inv = rsqrtf(q * (1.0f / 128.0f) + 1e-5f);
    float4 wv = ((const float4*)w)[lane];
    float4 bv = ((const float4*)b)[lane];
    uint2 pk;
    pk.x = pack_bf2(dx * inv * wv.x + bv.x, dy * inv * wv.y + bv.y);
    pk.y = pack_bf2(dz * inv * wv.z + bv.z, dw * inv * wv.w + bv.w);
    *(uint2*)(g_xw_bf + (size_t)row * CC + lane * 4) = pk;
}

// ---------------- LN2 -> bf16 ----------------
__global__ void ln2_kernel(const float* __restrict__ w, const float* __restrict__ b) {
    int row  = blockIdx.x * 8 + (threadIdx.x >> 5);
    int lane = threadIdx.x & 31;
    float4 v = ((const float4*)(g_xres + (size_t)row * CC))[lane];
    float s = v.x + v.y + v.z + v.w;
    #pragma unroll
    for (int o = 16; o; o >>= 1) s += __shfl_xor_sync(0xffffffffu, s, o);
    float mean = s * (1.0f / 128.0f);
    float dx = v.x - mean, dy = v.y - mean, dz = v.z - mean, dw = v.w - mean;
    float q = dx*dx + dy*dy + dz*dz + dw*dw;
    #pragma unroll
    for (int o = 16; o; o >>= 1) q += __shfl_xor_sync(0xffffffffu, q, o);
    float inv = rsqrtf(q * (1.0f / 128.0f) + 1e-5f);
    float4 wv = ((const float4*)w)[lane];
    float4 bv = ((const float4*)b)[lane];
    uint2 pk;
    pk.x = pack_bf2(dx * inv * wv.x + bv.x, dy * inv * wv.y + bv.y);
    pk.y = pack_bf2(dz * inv * wv.z + bv.z, dw * inv * wv.w + bv.w);
    *(uint2*)(g_y_bf + (size_t)row * CC + lane * 4) = pk;
}

// =====================================================================
// GEMM machinery (as round 6): 128x128 tile, 8 warps, ldmatrix + mma
// =====================================================================
#define SMTOT 73728

template<int MODE>
__device__ __forceinline__ void gemm_epilogue(
    float acc[2][8][4], int yb, int m0, int wm, int wn, int g, int t,
    const float* __restrict__ bias, const float* __restrict__ xin,
    float* __restrict__ outp) {
    #pragma unroll
    for (int mi = 0; mi < 2; ++mi) {
        #pragma unroll
        for (int half = 0; half < 2; ++half) {
            int m = m0 + wm + mi * 16 + g + half * 8;
            if (MODE == 0) {
                int bn = m / NN, n = m - bn * NN;
                __nv_bfloat16* dst = (yb == 0) ? g_q_bf : (yb == 1) ? g_k_bf : g_v_bf;
                float scl = (yb == 0) ? SCALEF : 1.0f;
                #pragma unroll
                for (int ni = 0; ni < 8; ++ni) {
                    int ol = wn + ni * 8 + 2 * t;
                    int hh = ol >> 5, dd = ol & 31;
                    float vx = (acc[mi][ni][half*2+0] + bias[yb * 128 + ol])     * scl;
                    float vy = (acc[mi][ni][half*2+1] + bias[yb * 128 + ol + 1]) * scl;
                    *(uint32_t*)(dst + (size_t)(bn * NH4 + hh) * (NN * HD32) + n * HD32 + dd) =
                        pack_bf2(vx, vy);
                }
            } else if (MODE == 1) {
                int bn = m / NN, n = m - bn * NN;
                int bi = bn >> 8, win = bn & 255;
                int wi = win >> 4, wj = win & 15;
                int r = n / 7, cq = n - r * 7;
                int ii = wi * 7 + r + SHIFT3;  if (ii >= HH) ii -= HH;
                int jj = wj * 7 + cq + SHIFT3; if (jj >= WW) jj -= WW;
                size_t tok = (size_t)bi * LTOK + ii * WW + jj;
                #pragma unroll
                for (int ni = 0; ni < 8; ++ni) {
                    int ol = wn + ni * 8 + 2 * t;
                    float2 xr = *(const float2*)(xin + tok * CC + ol);
                    float2 v;
                    v.x = acc[mi][ni][half*2+0] + bias[ol]     + xr.x;
                    v.y = acc[mi][ni][half*2+1] + bias[ol + 1] + xr.y;
                    *(float2*)(g_xres + tok * CC + ol) = v;
                }
            } else if (MODE == 2) {
                #pragma unroll
                for (int ni = 0; ni < 8; ++ni) {
                    int ol = wn + ni * 8 + 2 * t;
                    float a = acc[mi][ni][half*2+0] + bias[yb * 128 + ol];
                    float b = acc[mi][ni][half*2+1] + bias[yb * 128 + ol + 1];
                    float ga = 0.5f * a * (1.0f + erff(a * 0.70710678118654752f));
                    float gb = 0.5f * b * (1.0f + erff(b * 0.70710678118654752f));
                    *(uint32_t*)(g_h1_bf + (size_t)m * HID + yb * 128 + ol) = pack_bf2(ga, gb);
                }
            } else {
                #pragma unroll
                for (int ni = 0; ni < 8; ++ni) {
                    int ol = wn + ni * 8 + 2 * t;
                    float2 xr = *(const float2*)(g_xres + (size_t)m * CC + ol);
                    float2 v;
                    v.x = acc[mi][ni][half*2+0] + bias[ol]     + xr.x;
                    v.y = acc[mi][ni][half*2+1] + bias[ol + 1] + xr.y;
                    *(float2*)(outp + (size_t)m * CC + ol) = v;
                }
            }
        }
    }
}

__device__ __forceinline__ void gemm_chunk_mma(
    float acc[2][8][4], uint32_t Ab, uint32_t Bb,
    int wm, int wn, uint32_t a_lane_off, uint32_t b_lane_off) {
    #pragma unroll
    for (int kk2 = 0; kk2 < 32; kk2 += 8) {
        uint32_t af[2][4];
        #pragma unroll
        for (int mi = 0; mi < 2; ++mi)
            LDSM4(af[mi][0], af[mi][1], af[mi][2], af[mi][3],
                  Ab + (wm + mi * 16) * 144 + kk2 * 4 + a_lane_off);
        uint32_t bf[8][2];
        #pragma unroll
        for (int p = 0; p < 4; ++p)
            LDSM4(bf[2*p][0], bf[2*p][1], bf[2*p+1][0], bf[2*p+1][1],
                  Bb + (wn + p * 16) * 144 + kk2 * 4 + b_lane_off);
        #pragma unroll
        for (int mi = 0; mi < 2; ++mi)
            #pragma unroll
            for (int ni = 0; ni < 8; ++ni)
                mma_bf16(acc[mi][ni][0], acc[mi][ni][1], acc[mi][ni][2], acc[mi][ni][3],
                         af[mi][0], af[mi][1], af[mi][2], af[mi][3],
                         bf[ni][0], bf[ni][1]);
    }
}

template<int NB, int MODE>
__global__ void __launch_bounds__(256, 2)
gemm_multi(const __nv_bfloat16* __restrict__ A, const __nv_bfloat16* __restrict__ Wb,
           const float* __restrict__ bias, const float* __restrict__ xin,
           float* __restrict__ outp) {
    extern __shared__ char smem[];
    const uint32_t sbase = smem_u32(smem);
    const int m0 = blockIdx.x * 128;
    const int tid  = threadIdx.x;
    const int wid  = tid >> 5;
    const int lane = tid & 31;
    const int g = lane >> 2;
    const int t = lane & 3;
    const int wm = (wid >> 1) * 32;
    const int wn = (wid & 1) * 64;
    const uint32_t a_lane_off = ((lane & 7) + ((lane >> 3) & 1) * 8) * 144 + (lane >> 4) * 16;
    const uint32_t b_lane_off = (((lane >> 4) & 1) * 8 + (lane & 7)) * 144 + ((lane >> 3) & 1) * 16;

    #pragma unroll
    for (int it = 0; it < 8; ++it) {
        int idx = tid + it * 256;
        int r = idx >> 4, cc = idx & 15;
        uint32_t da = sbase + (cc >> 3) * 18432 + r * 144 + (cc & 7) * 16;
        CP_ASYNC16(da, A + (size_t)(m0 + r) * 128 + cc * 8);
    }
    #pragma unroll
    for (int it = 0; it < 4; ++it) {
        int idx = tid + it * 256;
        int r = idx >> 3, cc2 = idx & 7;
        CP_ASYNC16(sbase + 36864 + r * 144 + cc2 * 16, Wb + (size_t)r * 128 + cc2 * 8);
    }
    CP_COMMIT();

    float acc[2][8][4];
    #pragma unroll 1
    for (int s = 0; s < 2 * NB; ++s) {
        int c = s & 1, buf = s & 1, yb = s >> 1;
        if (c == 0) {
            #pragma unroll
            for (int mi = 0; mi < 2; ++mi)
                #pragma unroll
                for (int ni = 0; ni < 8; ++ni)
                    #pragma unroll
                    for (int q = 0; q < 4; ++q) acc[mi][ni][q] = 0.0f;
        }
        if (s + 1 < 2 * NB) {
            int yb2 = (s + 1) >> 1, c2 = (s + 1) & 1, buf2 = (s + 1) & 1;
            #pragma unroll
            for (int it = 0; it < 4; ++it) {
                int idx = tid + it * 256;
                int r = idx >> 3, cc2 = idx & 7;
                CP_ASYNC16(sbase + 36864 + buf2 * 18432 + r * 144 + cc2 * 16,
                           Wb + (size_t)(yb2 * 128 + r) * 128 + c2 * 64 + cc2 * 8);
            }
            CP_COMMIT();
            CP_WAIT1();
        } else {
            CP_WAIT0();
        }
        __syncthreads();
        gemm_chunk_mma(acc, sbase + c * 18432, sbase + 36864 + buf * 18432,
                       wm, wn, a_lane_off, b_lane_off);
        __syncthreads();
        if (c == 1)
            gemm_epilogue<MODE>(acc, yb, m0, wm, wn, g, t, bias, xin, outp);
    }
}

template<int KDIM, int MODE>
__global__ void __launch_bounds__(256, 2)
gemm_stream(const __nv_bfloat16* __restrict__ A, const __nv_bfloat16* __restrict__ Wb,
            const float* __restrict__ bias, const float* __restrict__ xin,
            float* __restrict__ outp) {
    extern __shared__ char smem[];
    const uint32_t sbase = smem_u32(smem);
    const int m0 = blockIdx.x * 128;
    const int tid  = threadIdx.x;
    const int wid  = tid >> 5;
    const int lane = tid & 31;
    const int g = lane >> 2;
    const int t = lane & 3;
    const int wm = (wid >> 1) * 32;
    const int wn = (wid & 1) * 64;
    const uint32_t a_lane_off = ((lane & 7) + ((lane >> 3) & 1) * 8) * 144 + (lane >> 4) * 16;
    const uint32_t b_lane_off = (((lane >> 4) & 1) * 8 + (lane & 7)) * 144 + ((lane >> 3) & 1) * 16;
    const int NC = KDIM / 64;

    float acc[2][8][4];
    #pragma unroll
    for (int mi = 0; mi < 2; ++mi)
        #pragma unroll
        for (int ni = 0; ni < 8; ++ni)
            #pragma unroll
            for (int q = 0; q < 4; ++q) acc[mi][ni][q] = 0.0f;

    #pragma unroll
    for (int it = 0; it < 4; ++it) {
        int idx = tid + it * 256;
        int r = idx >> 3, cc = idx & 7;
        uint32_t da = sbase + r * 144 + cc * 16;
        CP_ASYNC16(da, A + (size_t)(m0 + r) * KDIM + cc * 8);
        CP_ASYNC16(da + 18432, Wb + (size_t)r * KDIM + cc * 8);
    }
    CP_COMMIT();

    #pragma unroll 1
    for (int c = 0; c < NC; ++c) {
        if (c + 1 < NC) {
            int k0 = (c + 1) * 64;
            int sel = (c + 1) & 1;
            #pragma unroll
            for (int it = 0; it < 4; ++it) {
                int idx = tid + it * 256;
                int r = idx >> 3, cc = idx & 7;
                uint32_t da = sbase + sel * 36864 + r * 144 + cc * 16;
                CP_ASYNC16(da, A + (size_t)(m0 + r) * KDIM + k0 + cc * 8);
                CP_ASYNC16(da + 18432, Wb + (size_t)r * KDIM + k0 + cc * 8);
            }
            CP_COMMIT();
            CP_WAIT1();
        } else {
            CP_WAIT0();
        }
        __syncthreads();
        uint32_t base = sbase + (c & 1) * 36864;
        gemm_chunk_mma(acc, base, base + 18432, wm, wn, a_lane_off, b_lane_off);
        __syncthreads();
    }
    gemm_epilogue<MODE>(acc, 0, m0, wm, wn, g, t, bias, xin, outp);
}

// ---------------- tensor-core windowed attention ----------------
// One CTA per window (2048 CTAs, 256 thr = 8 warps). Warp w: head h=w>>1,
// row-half wp=w&1 (query rows wp*32..wp*32+31 of 64-padded).
// QK^T via mma (A=Q ldmatrix, B=K ldmatrix), softmax in registers (quad shfl),
// P repacked in registers as A-frags, V via ldmatrix.trans as B-frags.
__device__ __forceinline__ int regionf(int i) { return (i < 105) ? 0 : ((i < 109) ? 1 : 2); }

#define ATT_STR 40                      // bf16 per smem row (80 B)
#define ATT_Q   0
#define ATT_K   20480
#define ATT_V   40960
#define ATT_BS  61440
#define ATT_SM  (61440 + 4*169*4)       // 64144 B

__global__ void __launch_bounds__(256, 2)
attn_kernel(const float* __restrict__ rpb) {
    extern __shared__ char smem[];
    const uint32_t sbase = smem_u32(smem);
    __nv_bfloat16* qs = (__nv_bfloat16*)(smem + ATT_Q);
    __nv_bfloat16* ks = (__nv_bfloat16*)(smem + ATT_K);
    __nv_bfloat16* vs = (__nv_bfloat16*)(smem + ATT_V);
    float* bs = (float*)(smem + ATT_BS);

    int bn = blockIdx.x;
    int tid = threadIdx.x;
    int wid = tid >> 5, lane = tid & 31;
    int h = wid >> 1, wp = wid & 1;
    int g = lane >> 2, t = lane & 3;

    // stage q/k/v: (bn,h,49,32) bf16 -> smem [h][64][40], rows 49-63 zeroed
    {
        const uint4* qsrc = (const uint4*)(g_q_bf + (size_t)bn * (NH4*NN*HD32));
        const uint4* ksrc = (const uint4*)(g_k_bf + (size_t)bn * (NH4*NN*HD32));
        const uint4* vsrc = (const uint4*)(g_v_bf + (size_t)bn * (NH4*NN*HD32));
        for (int i = tid; i < 784; i += 256) {
            int hh = i / 196, rem = i - hh * 196;
            int tok = rem >> 2, seg = rem & 3;
            int off = (hh * 64 + tok) * ATT_STR + seg * 8;
            *(uint4*)(qs + off) = qsrc[i];
            *(uint4*)(ks + off) = ksrc[i];
            *(uint4*)(vs + off) = vsrc[i];
        }
        uint4 z = {0, 0, 0, 0};
        for (int i = tid; i < 240; i += 256) {   // 4h * 15 rows * 4 segs
            int hh = i / 60, rem = i - hh * 60;
            int tok = 49 + (rem >> 2), seg = rem & 3;
            int off = (hh * 64 + tok) * ATT_STR + seg * 8;
            *(uint4*)(qs + off) = z;
            *(uint4*)(ks + off) = z;
            *(uint4*)(vs + off) = z;
        }
        for (int i = tid; i < 676; i += 256)
            bs[i] = rpb[(i % 169) * 4 + (i / 169)];
    }
    __syncthreads();

    const uint32_t qb = sbase + ATT_Q + (h * 64 + wp * 32) * 80;
    const uint32_t kb = sbase + ATT_K + h * 64 * 80;
    const uint32_t vb = sbase + ATT_V + h * 64 * 80;
    const uint32_t a_off = ((lane & 7) + ((lane >> 3) & 1) * 8) * 80 + (lane >> 4) * 16;
    const uint32_t b_off = (((lane >> 4) & 1) * 8 + (lane & 7)) * 80 + ((lane >> 3) & 1) * 16;

    // ---- S = Q K^T : warp computes 32x64, K(d)=32 -> 2 k16 steps ----
    float sacc[2][8][4];
    #pragma unroll
    for (int mi = 0; mi < 2; ++mi)
        #pragma unroll
        for (int ni = 0; ni < 8; ++ni)
            #pragma unroll
            for (int q = 0; q < 4; ++q) sacc[mi][ni][q] = 0.0f;
    #pragma unroll
    for (int kt = 0; kt < 2; ++kt) {
        uint32_t af[2][4];
        #pragma unroll
        for (int mi = 0; mi < 2; ++mi)
            LDSM4(af[mi][0], af[mi][1], af[mi][2], af[mi][3],
                  qb + mi * 16 * 80 + kt * 32 + a_off);
        uint32_t bf[8][2];
        #pragma unroll
        for (int p = 0; p < 4; ++p)
            LDSM4(bf[2*p][0], bf[2*p][1], bf[2*p+1][0], bf[2*p+1][1],
                  kb + p * 16 * 80 + kt * 32 + b_off);
        #pragma unroll
        for (int mi = 0; mi < 2; ++mi)
            #pragma unroll
            for (int ni = 0; ni < 8; ++ni)
                mma_bf16(sacc[mi][ni][0], sacc[mi][ni][1], sacc[mi][ni][2], sacc[mi][ni][3],
                         af[mi][0], af[mi][1], af[mi][2], af[mi][3],
                         bf[ni][0], bf[ni][1]);
    }

    // ---- bias + shift-mask + softmax in registers ----
    int win = bn & 255, wi = win >> 4, wj = win & 15;
    // col metadata for the 16 cols this thread owns (m = ni*8 + 2t + j)
    int creg[8][2], cr2[8][2], cc2a[8][2];
    #pragma unroll
    for (int ni = 0; ni < 8; ++ni)
        #pragma unroll
        for (int j = 0; j < 2; ++j) {
            int m = ni * 8 + 2 * t + j;
            int r2 = m / 7, c2 = m - r2 * 7;
            cr2[ni][j] = r2; cc2a[ni][j] = c2;
            creg[ni][j] = regionf(wi * 7 + r2) * 3 + regionf(wj * 7 + c2);
        }
    #pragma unroll
    for (int mi = 0; mi < 2; ++mi) {
        #pragma unroll
        for (int half = 0; half < 2; ++half) {
            int r = wp * 32 + mi * 16 + g + half * 8;
            bool rv = (r < NN);
            int r1 = r / 7, c1 = r - r1 * 7;
            int reg1 = rv ? regionf(wi * 7 + r1) * 3 + regionf(wj * 7 + c1) : 0;
            float mx = -1e30f;
            #pragma unroll
            for (int ni = 0; ni < 8; ++ni)
                #pragma unroll
                for (int j = 0; j < 2; ++j) {
                    int m = ni * 8 + 2 * t + j;
                    if (rv && m < NN) {
                        float v = sacc[mi][ni][half*2+j]
                                + bs[h * 169 + (r1 - cr2[ni][j] + 6) * 13 + (c1 - cc2a[ni][j] + 6)];
                        if (reg1 != creg[ni][j]) v -= 100.0f;
                        sacc[mi][ni][half*2+j] = v;
                        mx = fmaxf(mx, v);
                    }
                }
            mx = fmaxf(mx, __shfl_xor_sync(0xffffffffu, mx, 1));
            mx = fmaxf(mx, __shfl_xor_sync(0xffffffffu, mx, 2));
            float sum = 0.0f;
            #pragma unroll
            for (int ni = 0; ni < 8; ++ni)
                #pragma unroll
                for (int j = 0; j < 2; ++j) {
                    int m = ni * 8 + 2 * t + j;
                    float e = (rv && m < NN) ? __expf(sacc[mi][ni][half*2+j] - mx) : 0.0f;
                    sacc[mi][ni][half*2+j] = e;
                    sum += e;
                }
            sum += __shfl_xor_sync(0xffffffffu, sum, 1);
            sum += __shfl_xor_sync(0xffffffffu, sum, 2);
            float inv = rv ? 1.0f / sum : 0.0f;
            #pragma unroll
            for (int ni = 0; ni < 8; ++ni)
                #pragma unroll
                for (int j = 0; j < 2; ++j)
                    sacc[mi][ni][half*2+j] *= inv;
        }
    }

    // ---- O = P V : P repacked from sacc, V via ldmatrix.trans ----
    float oacc[2][4][4];
    #pragma unroll
    for (int mi = 0; mi < 2; ++mi)
        #pragma unroll
        for (int nd = 0; nd < 4; ++nd)
            #pragma unroll
            for (int q = 0; q < 4; ++q) oacc[mi][nd][q] = 0.0f;
    #pragma unroll
    for (int kt = 0; kt < 4; ++kt) {
        uint32_t pa[2][4];
        #pragma unroll
        for (int mi = 0; mi < 2; ++mi) {
            pa[mi][0] = pack_bf2(sacc[mi][2*kt][0],   sacc[mi][2*kt][1]);
            pa[mi][1] = pack_bf2(sacc[mi][2*kt][2],   sacc[mi][2*kt][3]);
            pa[mi][2] = pack_bf2(sacc[mi][2*kt+1][0], sacc[mi][2*kt+1][1]);
            pa[mi][3] = pack_bf2(sacc[mi][2*kt+1][2], sacc[mi][2*kt+1][3]);
        }
        uint32_t vf[4][2];
        #pragma unroll
        for (int dh = 0; dh < 2; ++dh) {
            uint32_t r0, r1, r2, r3;
            LDSM4T(r0, r1, r2, r3,
                   vb + (kt * 16 + ((lane >> 3) & 1) * 8 + (lane & 7)) * 80
                      + dh * 32 + (lane >> 4) * 16);
            vf[dh*2][0]   = r0; vf[dh*2][1]   = r1;
            vf[dh*2+1][0] = r2; vf[dh*2+1][1] = r3;
        }
        #pragma unroll
        for (int mi = 0; mi < 2; ++mi)
            #pragma unroll
            for (int nd = 0; nd < 4; ++nd)
                mma_bf16(oacc[mi][nd][0], oacc[mi][nd][1], oacc[mi][nd][2], oacc[mi][nd][3],
                         pa[mi][0], pa[mi][1], pa[mi][2], pa[mi][3],
                         vf[nd][0], vf[nd][1]);
    }

    // ---- store O (rows < 49) ----
    #pragma unroll
    for (int mi = 0; mi < 2; ++mi)
        #pragma unroll
        for (int half = 0; half < 2; ++half) {
            int r = wp * 32 + mi * 16 + g + half * 8;
            if (r < NN) {
                __nv_bfloat16* o = g_obuf_bf + ((size_t)(bn * NN + r)) * CC + h * HD32;
                #pragma unroll
                for (int nd = 0; nd < 4; ++nd)
                    *(uint32_t*)(o + nd * 8 + 2 * t) =
                        pack_bf2(oacc[mi][nd][half*2+0], oacc[mi][nd][half*2+1]);
            }
        }
}

// ---------------- launch ----------------
extern "C" void kernel_launch(void* const* d_in, const int* in_sizes, int n_in,
                              void* d_out, int out_size) {
    const float* x       = (const float*)d_in[0];
    const float* norm1_w = (const float*)d_in[2];
    const float* norm1_b = (const float*)d_in[3];
    const float* qkv_w   = (const float*)d_in[4];
    const float* qkv_b   = (const float*)d_in[5];
    const float* rpb     = (const float*)d_in[6];
    const float* proj_w  = (const float*)d_in[7];
    const float* proj_b  = (const float*)d_in[8];
    const float* norm2_w = (const float*)d_in[9];
    const float* norm2_b = (const float*)d_in[10];
    const float* fc1_w   = (const float*)d_in[11];
    const float* fc1_b   = (const float*)d_in[12];
    const float* fc2_w   = (const float*)d_in[13];
    const float* fc2_b   = (const float*)d_in[14];
    float* out = (float*)d_out;

    cudaFuncSetAttribute(gemm_multi<3, 0>, cudaFuncAttributeMaxDynamicSharedMemorySize, SMTOT);
    cudaFuncSetAttribute(gemm_multi<1, 1>, cudaFuncAttributeMaxDynamicSharedMemorySize, SMTOT);
    cudaFuncSetAttribute(gemm_multi<4, 2>, cudaFuncAttributeMaxDynamicSharedMemorySize, SMTOT);
    cudaFuncSetAttribute(gemm_stream<512, 3>, cudaFuncAttributeMaxDynamicSharedMemorySize, SMTOT);
    cudaFuncSetAttribute(attn_kernel, cudaFuncAttributeMaxDynamicSharedMemorySize, ATT_SM);

    __nv_bfloat16 *p_qkvw, *p_projw, *p_fc1w, *p_fc2w;
    __nv_bfloat16 *p_xw, *p_obuf, *p_y, *p_h1;
    cudaGetSymbolAddress((void**)&p_qkvw, g_qkvw);
    cudaGetSymbolAddress((void**)&p_projw, g_projw);
    cudaGetSymbolAddress((void**)&p_fc1w, g_fc1w);
    cudaGetSymbolAddress((void**)&p_fc2w, g_fc2w);
    cudaGetSymbolAddress((void**)&p_xw, g_xw_bf);
    cudaGetSymbolAddress((void**)&p_obuf, g_obuf_bf);
    cudaGetSymbolAddress((void**)&p_y, g_y_bf);
    cudaGetSymbolAddress((void**)&p_h1, g_h1_bf);

    cvt_all<<<192, 256>>>(qkv_w, proj_w, fc1_w, fc2_w);
    ln1_gather_kernel<<<MROWS / 8, 256>>>(x, norm1_w, norm1_b);
    gemm_multi<3, 0><<<MROWS / 128, 256, SMTOT>>>(p_xw, p_qkvw, qkv_b, nullptr, nullptr);
    attn_kernel<<<BB * NW, 256, ATT_SM>>>(rpb);
    gemm_multi<1, 1><<<MROWS / 128, 256, SMTOT>>>(p_obuf, p_projw, proj_b, x, nullptr);
    ln2_kernel<<<MROWS / 8, 256>>>(norm2_w, norm2_b);
    gemm_multi<4, 2><<<MROWS / 128, 256, SMTOT>>>(p_y, p_fc1w, fc1_b, nullptr, nullptr);
    gemm_stream<512, 3><<<MROWS / 128, 256, SMTOT>>>(p_h1, p_fc2w, fc2_b, nullptr, out);
}